// round 2
// baseline (speedup 1.0000x reference)
#include <cuda_runtime.h>
#include <cuda_bf16.h>
#include <math.h>

#define MAXN 100000
#define MAXE 1600000
#define NGRAPH 512

// ------------------------- device scratch ----------
__device__ float g_A[(size_t)MAXN * 128];   // GEMM output (hs = dinv * x@W)
__device__ float g_B[(size_t)MAXN * 128];   // aggregation output (BN input)
__device__ int   g_deg[MAXN];
__device__ int   g_tmp[MAXN];
__device__ int   g_rowptr[MAXN + 1];
__device__ int   g_cursor[MAXN];
__device__ int   g_col[MAXE];
__device__ float g_dinv[MAXN];
__device__ int   g_bsums[128];
__device__ float g_stats[1024];             // [0,64)=L1 [64,192)=L2 [192,448)=L3 [448,704)=L4
__device__ unsigned g_poolu[NGRAPH * 128];  // order-encoded float max
__device__ float g_q[NGRAPH * 128];

// order-preserving float<->uint encoding (monotone for all finite floats)
__device__ __forceinline__ unsigned enc_f(float f) {
    unsigned b = __float_as_uint(f);
    return (b & 0x80000000u) ? ~b : (b | 0x80000000u);
}
__device__ __forceinline__ float dec_f(unsigned k) {
    unsigned b = (k & 0x80000000u) ? (k ^ 0x80000000u) : ~k;
    return __uint_as_float(b);
}

// ------------------------------- setup kernels ------------------------------
__global__ void zero_kernel(int n) {
    int i = blockIdx.x * blockDim.x + threadIdx.x;
    if (i < n) g_deg[i] = 0;
    if (i < 1024) g_stats[i] = 0.f;
    if (i < NGRAPH * 128) g_poolu[i] = 0u;   // below enc(-inf)=0x007fffff
}

__global__ void deg_kernel(const int* __restrict__ dst, int e) {
    int i = blockIdx.x * blockDim.x + threadIdx.x;
    if (i < e) atomicAdd(&g_deg[dst[i]], 1);
}

__global__ void scan_block_kernel(int n) {
    __shared__ int s[1024];
    int i = blockIdx.x * 1024 + threadIdx.x;
    int v = (i < n) ? g_deg[i] : 0;
    s[threadIdx.x] = v;
    __syncthreads();
    for (int off = 1; off < 1024; off <<= 1) {
        int t = (threadIdx.x >= off) ? s[threadIdx.x - off] : 0;
        __syncthreads();
        s[threadIdx.x] += t;
        __syncthreads();
    }
    if (i < n) g_tmp[i] = s[threadIdx.x];
    if (threadIdx.x == 1023) g_bsums[blockIdx.x] = s[1023];
}

__global__ void scan_sums_kernel(int nb) {
    __shared__ int s[128];
    int t = threadIdx.x;
    int v = (t < nb) ? g_bsums[t] : 0;
    s[t] = v;
    __syncthreads();
    for (int off = 1; off < 128; off <<= 1) {
        int u = (t >= off) ? s[t - off] : 0;
        __syncthreads();
        s[t] += u;
        __syncthreads();
    }
    if (t < nb) g_bsums[t] = s[t] - v;   // exclusive
}

__global__ void scan_fin_kernel(int n) {
    int i = blockIdx.x * blockDim.x + threadIdx.x;
    if (i >= n) return;
    int incl = g_tmp[i] + g_bsums[i >> 10];
    g_rowptr[i + 1] = incl;
    g_cursor[i] = incl - g_deg[i];
    g_dinv[i] = rsqrtf((float)(g_deg[i] + 1));
    if (i == 0) g_rowptr[0] = 0;
}

__global__ void fill_kernel(const int* __restrict__ src, const int* __restrict__ dst, int e) {
    int i = blockIdx.x * blockDim.x + threadIdx.x;
    if (i < e) {
        int p = atomicAdd(&g_cursor[dst[i]], 1);
        g_col[p] = src[i];
    }
}

// ------------------------------- GEMM kernels --------------------------------
__global__ void gemm1_kernel(const float* __restrict__ x, const float* __restrict__ W, int n) {
    __shared__ float Ws[6 * 32];
    int tid = threadIdx.x;
    if (tid < 6 * 32) Ws[tid] = W[tid];
    __syncthreads();
    int i = blockIdx.x * blockDim.x + tid;
    if (i >= n) return;
    float xv[6];
#pragma unroll
    for (int k = 0; k < 6; k++) xv[k] = x[(size_t)i * 6 + k];
    float dv = g_dinv[i];
    size_t base = (size_t)i * 32;
#pragma unroll
    for (int c = 0; c < 32; c++) {
        float acc = 0.f;
#pragma unroll
        for (int k = 0; k < 6; k++) acc = fmaf(xv[k], Ws[k * 32 + c], acc);
        g_A[base + c] = dv * acc;
    }
}

// Layer 2: relu(bn1(g_B[N,32])) @ W2[32,64] * dinv -> g_A. 64 nodes / 256-thread block.
__global__ void gemm2_kernel(const float* __restrict__ W,
                             const float* __restrict__ gamma, const float* __restrict__ beta,
                             float invn, int n) {
    __shared__ float Ws[32 * 64];
    __shared__ float ssc[32], ssh[32];
    int tid = threadIdx.x;
    for (int i = tid; i < 32 * 64; i += blockDim.x) Ws[i] = W[i];
    if (tid < 32) {
        float m = g_stats[tid] * invn;
        float var = g_stats[32 + tid] * invn - m * m;
        float s = gamma[tid] * rsqrtf(var + 1e-5f);
        ssc[tid] = s;
        ssh[tid] = fmaf(-m, s, beta[tid]);
    }
    __syncthreads();
    int lane = tid & 31;
    int warp = tid >> 5;
    float sc = ssc[lane], sh = ssh[lane];
    int base = blockIdx.x * 64 + warp * 8;
    int lim = min(base + 8, n);
    for (int gw = base; gw < lim; gw++) {
        float xv = g_B[(size_t)gw * 32 + lane];
        xv = fmaxf(fmaf(sc, xv, sh), 0.f);
        float a0 = 0.f, a1 = 0.f;
#pragma unroll
        for (int k = 0; k < 32; k++) {
            float v = __shfl_sync(0xffffffffu, xv, k);
            a0 = fmaf(v, Ws[k * 64 + lane], a0);
            a1 = fmaf(v, Ws[k * 64 + 32 + lane], a1);
        }
        float dv = g_dinv[gw];
        size_t ob = (size_t)gw * 64;
        g_A[ob + lane] = dv * a0;
        g_A[ob + 32 + lane] = dv * a1;
    }
}

// Layer 3: relu(bn2(g_B[N,64])) @ W3[64,128] * dinv -> g_A. 128 nodes / 256-thread block.
__global__ void gemm3_kernel(const float* __restrict__ W,
                             const float* __restrict__ gamma, const float* __restrict__ beta,
                             float invn, int n) {
    __shared__ float Ws[64 * 128];
    __shared__ float ssc[64], ssh[64];
    int tid = threadIdx.x;
    for (int i = tid; i < 64 * 128; i += blockDim.x) Ws[i] = W[i];
    if (tid < 64) {
        float m = g_stats[64 + tid] * invn;
        float var = g_stats[128 + tid] * invn - m * m;
        float s = gamma[tid] * rsqrtf(var + 1e-5f);
        ssc[tid] = s;
        ssh[tid] = fmaf(-m, s, beta[tid]);
    }
    __syncthreads();
    int lane = tid & 31;
    int warp = tid >> 5;
    float sc0 = ssc[lane], sh0 = ssh[lane];
    float sc1 = ssc[32 + lane], sh1 = ssh[32 + lane];
    int base = blockIdx.x * 128 + warp * 16;
    int lim = min(base + 16, n);
    for (int gw = base; gw < lim; gw++) {
        float x0 = g_B[(size_t)gw * 64 + lane];
        float x1 = g_B[(size_t)gw * 64 + 32 + lane];
        x0 = fmaxf(fmaf(sc0, x0, sh0), 0.f);
        x1 = fmaxf(fmaf(sc1, x1, sh1), 0.f);
        float a0 = 0.f, a1 = 0.f, a2 = 0.f, a3 = 0.f;
#pragma unroll
        for (int k = 0; k < 32; k++) {
            float v = __shfl_sync(0xffffffffu, x0, k);
            const float* w = &Ws[k * 128];
            a0 = fmaf(v, w[lane], a0);
            a1 = fmaf(v, w[32 + lane], a1);
            a2 = fmaf(v, w[64 + lane], a2);
            a3 = fmaf(v, w[96 + lane], a3);
        }
#pragma unroll
        for (int k = 0; k < 32; k++) {
            float v = __shfl_sync(0xffffffffu, x1, k);
            const float* w = &Ws[(32 + k) * 128];
            a0 = fmaf(v, w[lane], a0);
            a1 = fmaf(v, w[32 + lane], a1);
            a2 = fmaf(v, w[64 + lane], a2);
            a3 = fmaf(v, w[96 + lane], a3);
        }
        float dv = g_dinv[gw];
        size_t ob = (size_t)gw * 128;
        g_A[ob + lane] = dv * a0;
        g_A[ob + 32 + lane] = dv * a1;
        g_A[ob + 64 + lane] = dv * a2;
        g_A[ob + 96 + lane] = dv * a3;
    }
}

// ---------------------------- aggregation kernels ----------------------------
__global__ void agg32_kernel(const float* __restrict__ bias, int statoff, int n) {
    __shared__ float sred[64];
    int tid = threadIdx.x;
    if (tid < 64) sred[tid] = 0.f;
    __syncthreads();
    int lane = tid & 31;
    int nw = (gridDim.x * blockDim.x) >> 5;
    int gw = (blockIdx.x * blockDim.x + tid) >> 5;
    float b = bias[lane];
    float ps = 0.f, pq = 0.f;
    for (int d = gw; d < n; d += nw) {
        float acc = g_A[(size_t)d * 32 + lane];
        int beg = g_rowptr[d], end = g_rowptr[d + 1];
        for (int j = beg; j < end; j++) {
            acc += g_A[(size_t)g_col[j] * 32 + lane];
        }
        float o = fmaf(g_dinv[d], acc, b);
        g_B[(size_t)d * 32 + lane] = o;
        ps += o; pq += o * o;
    }
    atomicAdd(&sred[lane], ps);
    atomicAdd(&sred[32 + lane], pq);
    __syncthreads();
    if (tid < 64) atomicAdd(&g_stats[statoff + tid], sred[tid]);
}

__global__ void agg64_kernel(const float* __restrict__ bias, int statoff, int n) {
    __shared__ float sred[128];
    int tid = threadIdx.x;
    if (tid < 128) sred[tid] = 0.f;
    __syncthreads();
    int lane = tid & 31;
    int nw = (gridDim.x * blockDim.x) >> 5;
    int gw = (blockIdx.x * blockDim.x + tid) >> 5;
    int c0 = lane * 2;
    float b0 = bias[c0], b1 = bias[c0 + 1];
    float ps0 = 0.f, ps1 = 0.f, pq0 = 0.f, pq1 = 0.f;
    for (int d = gw; d < n; d += nw) {
        float2 acc = *(const float2*)&g_A[(size_t)d * 64 + c0];
        int beg = g_rowptr[d], end = g_rowptr[d + 1];
        for (int j = beg; j < end; j++) {
            float2 v = *(const float2*)&g_A[(size_t)g_col[j] * 64 + c0];
            acc.x += v.x; acc.y += v.y;
        }
        float dv = g_dinv[d];
        float o0 = fmaf(dv, acc.x, b0);
        float o1 = fmaf(dv, acc.y, b1);
        *(float2*)&g_B[(size_t)d * 64 + c0] = make_float2(o0, o1);
        ps0 += o0; ps1 += o1; pq0 += o0 * o0; pq1 += o1 * o1;
    }
    atomicAdd(&sred[c0], ps0);
    atomicAdd(&sred[c0 + 1], ps1);
    atomicAdd(&sred[64 + c0], pq0);
    atomicAdd(&sred[64 + c0 + 1], pq1);
    __syncthreads();
    for (int i = tid; i < 128; i += blockDim.x) atomicAdd(&g_stats[statoff + i], sred[i]);
}

// Layer-3 aggregation: compute raw o (pre-BN), accumulate stats, and pool raw max
// per graph (batch is sorted -> warp-local running max, flush on graph change).
// No g_B write. BN3+ReLU applied later to pooled values (monotone: gamma=1>0).
__global__ void agg128p_kernel(const float* __restrict__ bias,
                               const int* __restrict__ batch, int statoff, int n) {
    __shared__ float sred[256];
    int tid = threadIdx.x;
    if (tid < 256) sred[tid] = 0.f;
    __syncthreads();
    int lane = tid & 31;
    int nwarp = (gridDim.x * blockDim.x) >> 5;
    int w = (blockIdx.x * blockDim.x + tid) >> 5;
    int chunk = (n + nwarp - 1) / nwarp;
    int beg_d = w * chunk;
    int end_d = min(beg_d + chunk, n);
    int c0 = lane * 4;
    float4 b = *(const float4*)&bias[c0];
    float ps[4] = {0.f, 0.f, 0.f, 0.f};
    float pq[4] = {0.f, 0.f, 0.f, 0.f};
    float m[4] = {-INFINITY, -INFINITY, -INFINITY, -INFINITY};
    int cur = -1;
    for (int d = beg_d; d < end_d; d++) {
        int bg = batch[d];
        if (bg != cur) {
            if (cur >= 0) {
#pragma unroll
                for (int k = 0; k < 4; k++)
                    atomicMax(&g_poolu[cur * 128 + c0 + k], enc_f(m[k]));
            }
            cur = bg;
            m[0] = m[1] = m[2] = m[3] = -INFINITY;
        }
        float4 acc = *(const float4*)&g_A[(size_t)d * 128 + c0];
        int jb = g_rowptr[d], je = g_rowptr[d + 1];
        for (int j = jb; j < je; j++) {
            float4 v = *(const float4*)&g_A[(size_t)g_col[j] * 128 + c0];
            acc.x += v.x; acc.y += v.y; acc.z += v.z; acc.w += v.w;
        }
        float dv = g_dinv[d];
        float o0 = fmaf(dv, acc.x, b.x);
        float o1 = fmaf(dv, acc.y, b.y);
        float o2 = fmaf(dv, acc.z, b.z);
        float o3 = fmaf(dv, acc.w, b.w);
        ps[0] += o0; ps[1] += o1; ps[2] += o2; ps[3] += o3;
        pq[0] += o0 * o0; pq[1] += o1 * o1; pq[2] += o2 * o2; pq[3] += o3 * o3;
        m[0] = fmaxf(m[0], o0); m[1] = fmaxf(m[1], o1);
        m[2] = fmaxf(m[2], o2); m[3] = fmaxf(m[3], o3);
    }
    if (cur >= 0) {
#pragma unroll
        for (int k = 0; k < 4; k++)
            atomicMax(&g_poolu[cur * 128 + c0 + k], enc_f(m[k]));
    }
#pragma unroll
    for (int k = 0; k < 4; k++) {
        atomicAdd(&sred[c0 + k], ps[k]);
        atomicAdd(&sred[128 + c0 + k], pq[k]);
    }
    __syncthreads();
    for (int i = tid; i < 256; i += blockDim.x) atomicAdd(&g_stats[statoff + i], sred[i]);
}

// --------------------------------- final MLP ----------------------------------
// fc1: per-graph: decode pooled raw max, apply BN3+ReLU, @Wf1 + bf1, accumulate BN4 stats.
__global__ void fc1_kernel(const float* __restrict__ Wf1, const float* __restrict__ bf1,
                           const float* __restrict__ g3, const float* __restrict__ be3,
                           float invn) {
    __shared__ float pr[128];
    int g = blockIdx.x, t = threadIdx.x;
    {
        float mm = g_stats[192 + t] * invn;
        float var = g_stats[320 + t] * invn - mm * mm;
        float s = g3[t] * rsqrtf(var + 1e-5f);
        float sh = fmaf(-mm, s, be3[t]);
        float raw = dec_f(g_poolu[g * 128 + t]);
        pr[t] = fmaxf(fmaf(s, raw, sh), 0.f);
    }
    __syncthreads();
    float acc = bf1[t];
#pragma unroll 8
    for (int k = 0; k < 128; k++) acc = fmaf(pr[k], Wf1[k * 128 + t], acc);
    g_q[g * 128 + t] = acc;
    atomicAdd(&g_stats[448 + t], acc);
    atomicAdd(&g_stats[576 + t], acc * acc);
}

__global__ void fc2_kernel(const float* __restrict__ Wf2, const float* __restrict__ bf2,
                           const float* __restrict__ g4, const float* __restrict__ be4,
                           float* __restrict__ out) {
    __shared__ float r[128];
    __shared__ float red[64];
    int g = blockIdx.x, t = threadIdx.x;  // 64 threads
    const float invg = 1.0f / (float)NGRAPH;
#pragma unroll
    for (int h = 0; h < 2; h++) {
        int c = t + 64 * h;
        float mm = g_stats[448 + c] * invg;
        float var = g_stats[576 + c] * invg - mm * mm;
        float s = g4[c] * rsqrtf(var + 1e-5f);
        float sh = fmaf(-mm, s, be4[c]);
        r[c] = fmaxf(fmaf(s, g_q[g * 128 + c], sh), 0.f);
    }
    __syncthreads();
    float acc = bf2[t];
#pragma unroll 8
    for (int k = 0; k < 128; k++) acc = fmaf(r[k], Wf2[k * 64 + t], acc);
    red[t] = acc * acc;
    for (int off = 32; off > 0; off >>= 1) {
        __syncthreads();
        if (t < off) red[t] += red[t + off];
    }
    __syncthreads();
    float denom = fmaxf(sqrtf(red[0]), 1e-12f);
    out[g * 64 + t] = acc / denom;
}

// --------------------------------- launcher -----------------------------------
extern "C" void kernel_launch(void* const* d_in, const int* in_sizes, int n_in,
                              void* d_out, int out_size) {
    const float* x    = (const float*)d_in[0];
    const int* src    = (const int*)d_in[1];
    const int* dst    = (const int*)d_in[2];
    const int* batch  = (const int*)d_in[3];
    const float* W1  = (const float*)d_in[4];
    const float* b1  = (const float*)d_in[5];
    const float* G1  = (const float*)d_in[6];
    const float* be1 = (const float*)d_in[7];
    const float* W2  = (const float*)d_in[8];
    const float* b2  = (const float*)d_in[9];
    const float* G2  = (const float*)d_in[10];
    const float* be2 = (const float*)d_in[11];
    const float* W3  = (const float*)d_in[12];
    const float* b3  = (const float*)d_in[13];
    const float* G3  = (const float*)d_in[14];
    const float* be3 = (const float*)d_in[15];
    const float* Wf1 = (const float*)d_in[16];
    const float* bf1 = (const float*)d_in[17];
    const float* G4  = (const float*)d_in[18];
    const float* be4 = (const float*)d_in[19];
    const float* Wf2 = (const float*)d_in[20];
    const float* bf2 = (const float*)d_in[21];

    int n = in_sizes[0] / 6;
    int e = in_sizes[1];
    int nb = (n + 1023) / 1024;
    float invn = 1.0f / (float)n;

    int zmax = n > NGRAPH * 128 ? n : NGRAPH * 128;
    zero_kernel<<<(zmax + 255) / 256, 256>>>(n);
    deg_kernel<<<(e + 255) / 256, 256>>>(dst, e);
    scan_block_kernel<<<nb, 1024>>>(n);
    scan_sums_kernel<<<1, 128>>>(nb);
    scan_fin_kernel<<<(n + 255) / 256, 256>>>(n);
    fill_kernel<<<(e + 255) / 256, 256>>>(src, dst, e);

    // Layer 1
    gemm1_kernel<<<(n + 255) / 256, 256>>>(x, W1, n);
    agg32_kernel<<<2048, 256>>>(b1, 0, n);
    // Layer 2 (BN1 fused into gemm2)
    gemm2_kernel<<<(n + 63) / 64, 256>>>(W2, G1, be1, invn, n);
    agg64_kernel<<<2048, 256>>>(b2, 64, n);
    // Layer 3 (BN2 fused into gemm3)
    gemm3_kernel<<<(n + 127) / 128, 256>>>(W3, G2, be2, invn, n);
    // Aggregation + stats + fused raw max-pool (no g_B write)
    agg128p_kernel<<<512, 256>>>(b3, batch, 192, n);
    // MLP head (BN3 fused into fc1, BN4 fused into fc2)
    fc1_kernel<<<NGRAPH, 128>>>(Wf1, bf1, G3, be3, invn);
    fc2_kernel<<<NGRAPH, 64>>>(Wf2, bf2, G4, be4, (float*)d_out);
}

// round 3
// speedup vs baseline: 1.4476x; 1.4476x over previous
#include <cuda_runtime.h>
#include <cuda_bf16.h>
#include <math.h>

#define MAXN 100000
#define MAXE 1600000
#define NGRAPH 512

// ------------------------- device scratch ----------
__device__ float g_A[(size_t)MAXN * 128];   // GEMM output (hs = dinv * x@W)
__device__ float g_B[(size_t)MAXN * 128];   // aggregation output (BN input)
__device__ int   g_deg[MAXN];
__device__ int   g_tmp[MAXN];
__device__ int   g_rowptr[MAXN + 1];
__device__ int   g_cursor[MAXN];
__device__ int   g_col[MAXE];
__device__ float g_dinv[MAXN];
__device__ int   g_bsums[128];
__device__ float g_stats[1024];             // [0,64)=L1 [64,192)=L2 [192,448)=L3 [448,704)=L4
__device__ unsigned g_poolu[NGRAPH * 128];  // order-encoded float max
__device__ float g_q[NGRAPH * 128];

// order-preserving float<->uint encoding
__device__ __forceinline__ unsigned enc_f(float f) {
    unsigned b = __float_as_uint(f);
    return (b & 0x80000000u) ? ~b : (b | 0x80000000u);
}
__device__ __forceinline__ float dec_f(unsigned k) {
    unsigned b = (k & 0x80000000u) ? (k ^ 0x80000000u) : ~k;
    return __uint_as_float(b);
}

// ------------------------------- setup kernels ------------------------------
__global__ void zero_kernel(int n) {
    int i = blockIdx.x * blockDim.x + threadIdx.x;
    if (i < n) g_deg[i] = 0;
    if (i < 1024) g_stats[i] = 0.f;
    if (i < NGRAPH * 128) g_poolu[i] = 0u;
}

__global__ void deg_kernel(const int* __restrict__ dst, int e) {
    int i = blockIdx.x * blockDim.x + threadIdx.x;
    if (i < e) atomicAdd(&g_deg[dst[i]], 1);
}

__global__ void scan_block_kernel(int n) {
    __shared__ int s[1024];
    int i = blockIdx.x * 1024 + threadIdx.x;
    int v = (i < n) ? g_deg[i] : 0;
    s[threadIdx.x] = v;
    __syncthreads();
    for (int off = 1; off < 1024; off <<= 1) {
        int t = (threadIdx.x >= off) ? s[threadIdx.x - off] : 0;
        __syncthreads();
        s[threadIdx.x] += t;
        __syncthreads();
    }
    if (i < n) g_tmp[i] = s[threadIdx.x];
    if (threadIdx.x == 1023) g_bsums[blockIdx.x] = s[1023];
}

__global__ void scan_sums_kernel(int nb) {
    __shared__ int s[128];
    int t = threadIdx.x;
    int v = (t < nb) ? g_bsums[t] : 0;
    s[t] = v;
    __syncthreads();
    for (int off = 1; off < 128; off <<= 1) {
        int u = (t >= off) ? s[t - off] : 0;
        __syncthreads();
        s[t] += u;
        __syncthreads();
    }
    if (t < nb) g_bsums[t] = s[t] - v;   // exclusive
}

__global__ void scan_fin_kernel(int n) {
    int i = blockIdx.x * blockDim.x + threadIdx.x;
    if (i >= n) return;
    int incl = g_tmp[i] + g_bsums[i >> 10];
    g_rowptr[i + 1] = incl;
    g_cursor[i] = incl - g_deg[i];
    g_dinv[i] = rsqrtf((float)(g_deg[i] + 1));
    if (i == 0) g_rowptr[0] = 0;
}

__global__ void fill_kernel(const int* __restrict__ src, const int* __restrict__ dst, int e) {
    int i = blockIdx.x * blockDim.x + threadIdx.x;
    if (i < e) {
        int p = atomicAdd(&g_cursor[dst[i]], 1);
        g_col[p] = src[i];
    }
}

// ------------------------------- GEMM kernels --------------------------------
__global__ void gemm1_kernel(const float* __restrict__ x, const float* __restrict__ W, int n) {
    __shared__ float Ws[6 * 32];
    int tid = threadIdx.x;
    if (tid < 6 * 32) Ws[tid] = W[tid];
    __syncthreads();
    int i = blockIdx.x * blockDim.x + tid;
    if (i >= n) return;
    float xv[6];
#pragma unroll
    for (int k = 0; k < 6; k++) xv[k] = x[(size_t)i * 6 + k];
    float dv = g_dinv[i];
    size_t base = (size_t)i * 32;
#pragma unroll
    for (int c = 0; c < 32; c++) {
        float acc = 0.f;
#pragma unroll
        for (int k = 0; k < 6; k++) acc = fmaf(xv[k], Ws[k * 32 + c], acc);
        g_A[base + c] = dv * acc;
    }
}

// Layer 2: relu(bn1(g_B[N,32])) @ W2[32,64] * dinv -> g_A. Warp per node (R1 grid).
__global__ void gemm2_kernel(const float* __restrict__ W,
                             const float* __restrict__ gamma, const float* __restrict__ beta,
                             float invn, int n) {
    __shared__ float Ws[32 * 64];
    __shared__ float ssc[32], ssh[32];
    int tid = threadIdx.x;
    for (int i = tid; i < 32 * 64; i += blockDim.x) Ws[i] = W[i];
    if (tid < 32) {
        float m = g_stats[tid] * invn;
        float var = g_stats[32 + tid] * invn - m * m;
        float s = gamma[tid] * rsqrtf(var + 1e-5f);
        ssc[tid] = s;
        ssh[tid] = fmaf(-m, s, beta[tid]);
    }
    __syncthreads();
    int lane = tid & 31;
    int gw = (blockIdx.x * blockDim.x + tid) >> 5;
    if (gw >= n) return;
    float xv = g_B[(size_t)gw * 32 + lane];
    xv = fmaxf(fmaf(ssc[lane], xv, ssh[lane]), 0.f);
    float a0 = 0.f, a1 = 0.f;
#pragma unroll
    for (int k = 0; k < 32; k++) {
        float v = __shfl_sync(0xffffffffu, xv, k);
        a0 = fmaf(v, Ws[k * 64 + lane], a0);
        a1 = fmaf(v, Ws[k * 64 + 32 + lane], a1);
    }
    float dv = g_dinv[gw];
    size_t ob = (size_t)gw * 64;
    g_A[ob + lane] = dv * a0;
    g_A[ob + 32 + lane] = dv * a1;
}

// Layer 3: relu(bn2(g_B[N,64])) @ W3[64,128] * dinv -> g_A. Warp per node (R1 grid).
__global__ void gemm3_kernel(const float* __restrict__ W,
                             const float* __restrict__ gamma, const float* __restrict__ beta,
                             float invn, int n) {
    __shared__ float Ws[64 * 128];
    __shared__ float ssc[64], ssh[64];
    int tid = threadIdx.x;
    for (int i = tid; i < 64 * 128; i += blockDim.x) Ws[i] = W[i];
    if (tid < 64) {
        float m = g_stats[64 + tid] * invn;
        float var = g_stats[128 + tid] * invn - m * m;
        float s = gamma[tid] * rsqrtf(var + 1e-5f);
        ssc[tid] = s;
        ssh[tid] = fmaf(-m, s, beta[tid]);
    }
    __syncthreads();
    int lane = tid & 31;
    int gw = (blockIdx.x * blockDim.x + tid) >> 5;
    if (gw >= n) return;
    float x0 = g_B[(size_t)gw * 64 + lane];
    float x1 = g_B[(size_t)gw * 64 + 32 + lane];
    x0 = fmaxf(fmaf(ssc[lane], x0, ssh[lane]), 0.f);
    x1 = fmaxf(fmaf(ssc[32 + lane], x1, ssh[32 + lane]), 0.f);
    float a0 = 0.f, a1 = 0.f, a2 = 0.f, a3 = 0.f;
#pragma unroll
    for (int k = 0; k < 32; k++) {
        float v = __shfl_sync(0xffffffffu, x0, k);
        const float* w = &Ws[k * 128];
        a0 = fmaf(v, w[lane], a0);
        a1 = fmaf(v, w[32 + lane], a1);
        a2 = fmaf(v, w[64 + lane], a2);
        a3 = fmaf(v, w[96 + lane], a3);
    }
#pragma unroll
    for (int k = 0; k < 32; k++) {
        float v = __shfl_sync(0xffffffffu, x1, k);
        const float* w = &Ws[(32 + k) * 128];
        a0 = fmaf(v, w[lane], a0);
        a1 = fmaf(v, w[32 + lane], a1);
        a2 = fmaf(v, w[64 + lane], a2);
        a3 = fmaf(v, w[96 + lane], a3);
    }
    float dv = g_dinv[gw];
    size_t ob = (size_t)gw * 128;
    g_A[ob + lane] = dv * a0;
    g_A[ob + 32 + lane] = dv * a1;
    g_A[ob + 64 + lane] = dv * a2;
    g_A[ob + 96 + lane] = dv * a3;
}

// ---------------------------- aggregation kernels ----------------------------
__global__ void agg32_kernel(const float* __restrict__ bias, int statoff, int n) {
    __shared__ float sred[64];
    int tid = threadIdx.x;
    if (tid < 64) sred[tid] = 0.f;
    __syncthreads();
    int lane = tid & 31;
    int nw = (gridDim.x * blockDim.x) >> 5;
    int gw = (blockIdx.x * blockDim.x + tid) >> 5;
    float b = bias[lane];
    float ps = 0.f, pq = 0.f;
    for (int d = gw; d < n; d += nw) {
        float acc = g_A[(size_t)d * 32 + lane];
        int beg = g_rowptr[d], end = g_rowptr[d + 1];
        for (int j = beg; j < end; j++) {
            acc += g_A[(size_t)g_col[j] * 32 + lane];
        }
        float o = fmaf(g_dinv[d], acc, b);
        g_B[(size_t)d * 32 + lane] = o;
        ps += o; pq += o * o;
    }
    atomicAdd(&sred[lane], ps);
    atomicAdd(&sred[32 + lane], pq);
    __syncthreads();
    if (tid < 64) atomicAdd(&g_stats[statoff + tid], sred[tid]);
}

__global__ void agg64_kernel(const float* __restrict__ bias, int statoff, int n) {
    __shared__ float sred[128];
    int tid = threadIdx.x;
    if (tid < 128) sred[tid] = 0.f;
    __syncthreads();
    int lane = tid & 31;
    int nw = (gridDim.x * blockDim.x) >> 5;
    int gw = (blockIdx.x * blockDim.x + tid) >> 5;
    int c0 = lane * 2;
    float b0 = bias[c0], b1 = bias[c0 + 1];
    float ps0 = 0.f, ps1 = 0.f, pq0 = 0.f, pq1 = 0.f;
    for (int d = gw; d < n; d += nw) {
        float2 acc = *(const float2*)&g_A[(size_t)d * 64 + c0];
        int beg = g_rowptr[d], end = g_rowptr[d + 1];
        for (int j = beg; j < end; j++) {
            float2 v = *(const float2*)&g_A[(size_t)g_col[j] * 64 + c0];
            acc.x += v.x; acc.y += v.y;
        }
        float dv = g_dinv[d];
        float o0 = fmaf(dv, acc.x, b0);
        float o1 = fmaf(dv, acc.y, b1);
        *(float2*)&g_B[(size_t)d * 64 + c0] = make_float2(o0, o1);
        ps0 += o0; ps1 += o1; pq0 += o0 * o0; pq1 += o1 * o1;
    }
    atomicAdd(&sred[c0], ps0);
    atomicAdd(&sred[c0 + 1], ps1);
    atomicAdd(&sred[64 + c0], pq0);
    atomicAdd(&sred[64 + c0 + 1], pq1);
    __syncthreads();
    for (int i = tid; i < 128; i += blockDim.x) atomicAdd(&g_stats[statoff + i], sred[i]);
}

// Layer-3 aggregation + stats + fused raw max-pool (batch sorted; contiguous
// chunks of ~7 nodes per warp, flush atomicMax only at graph boundaries).
// 2048 blocks (R1-scale parallelism).
__global__ void agg128p_kernel(const float* __restrict__ bias,
                               const int* __restrict__ batch, int statoff, int n) {
    __shared__ float sred[256];
    int tid = threadIdx.x;
    if (tid < 256) sred[tid] = 0.f;
    __syncthreads();
    int lane = tid & 31;
    int nwarp = (gridDim.x * blockDim.x) >> 5;
    int w = (blockIdx.x * blockDim.x + tid) >> 5;
    int chunk = (n + nwarp - 1) / nwarp;
    int beg_d = w * chunk;
    int end_d = min(beg_d + chunk, n);
    int c0 = lane * 4;
    float4 b = *(const float4*)&bias[c0];
    float ps[4] = {0.f, 0.f, 0.f, 0.f};
    float pq[4] = {0.f, 0.f, 0.f, 0.f};
    float m[4] = {-INFINITY, -INFINITY, -INFINITY, -INFINITY};
    int cur = -1;
    for (int d = beg_d; d < end_d; d++) {
        int bg = batch[d];
        if (bg != cur) {
            if (cur >= 0) {
#pragma unroll
                for (int k = 0; k < 4; k++)
                    atomicMax(&g_poolu[cur * 128 + c0 + k], enc_f(m[k]));
            }
            cur = bg;
            m[0] = m[1] = m[2] = m[3] = -INFINITY;
        }
        float4 acc = *(const float4*)&g_A[(size_t)d * 128 + c0];
        int jb = g_rowptr[d], je = g_rowptr[d + 1];
        for (int j = jb; j < je; j++) {
            float4 v = *(const float4*)&g_A[(size_t)g_col[j] * 128 + c0];
            acc.x += v.x; acc.y += v.y; acc.z += v.z; acc.w += v.w;
        }
        float dv = g_dinv[d];
        float o0 = fmaf(dv, acc.x, b.x);
        float o1 = fmaf(dv, acc.y, b.y);
        float o2 = fmaf(dv, acc.z, b.z);
        float o3 = fmaf(dv, acc.w, b.w);
        ps[0] += o0; ps[1] += o1; ps[2] += o2; ps[3] += o3;
        pq[0] += o0 * o0; pq[1] += o1 * o1; pq[2] += o2 * o2; pq[3] += o3 * o3;
        m[0] = fmaxf(m[0], o0); m[1] = fmaxf(m[1], o1);
        m[2] = fmaxf(m[2], o2); m[3] = fmaxf(m[3], o3);
    }
    if (cur >= 0) {
#pragma unroll
        for (int k = 0; k < 4; k++)
            atomicMax(&g_poolu[cur * 128 + c0 + k], enc_f(m[k]));
    }
#pragma unroll
    for (int k = 0; k < 4; k++) {
        atomicAdd(&sred[c0 + k], ps[k]);
        atomicAdd(&sred[128 + c0 + k], pq[k]);
    }
    __syncthreads();
    for (int i = tid; i < 256; i += blockDim.x) atomicAdd(&g_stats[statoff + i], sred[i]);
}

// --------------------------------- final MLP ----------------------------------
__global__ void fc1_kernel(const float* __restrict__ Wf1, const float* __restrict__ bf1,
                           const float* __restrict__ g3, const float* __restrict__ be3,
                           float invn) {
    __shared__ float pr[128];
    int g = blockIdx.x, t = threadIdx.x;
    {
        float mm = g_stats[192 + t] * invn;
        float var = g_stats[320 + t] * invn - mm * mm;
        float s = g3[t] * rsqrtf(var + 1e-5f);
        float sh = fmaf(-mm, s, be3[t]);
        float raw = dec_f(g_poolu[g * 128 + t]);
        pr[t] = fmaxf(fmaf(s, raw, sh), 0.f);
    }
    __syncthreads();
    float acc = bf1[t];
#pragma unroll 8
    for (int k = 0; k < 128; k++) acc = fmaf(pr[k], Wf1[k * 128 + t], acc);
    g_q[g * 128 + t] = acc;
    atomicAdd(&g_stats[448 + t], acc);
    atomicAdd(&g_stats[576 + t], acc * acc);
}

__global__ void fc2_kernel(const float* __restrict__ Wf2, const float* __restrict__ bf2,
                           const float* __restrict__ g4, const float* __restrict__ be4,
                           float* __restrict__ out) {
    __shared__ float r[128];
    __shared__ float red[64];
    int g = blockIdx.x, t = threadIdx.x;  // 64 threads
    const float invg = 1.0f / (float)NGRAPH;
#pragma unroll
    for (int h = 0; h < 2; h++) {
        int c = t + 64 * h;
        float mm = g_stats[448 + c] * invg;
        float var = g_stats[576 + c] * invg - mm * mm;
        float s = g4[c] * rsqrtf(var + 1e-5f);
        float sh = fmaf(-mm, s, be4[c]);
        r[c] = fmaxf(fmaf(s, g_q[g * 128 + c], sh), 0.f);
    }
    __syncthreads();
    float acc = bf2[t];
#pragma unroll 8
    for (int k = 0; k < 128; k++) acc = fmaf(r[k], Wf2[k * 64 + t], acc);
    red[t] = acc * acc;
    for (int off = 32; off > 0; off >>= 1) {
        __syncthreads();
        if (t < off) red[t] += red[t + off];
    }
    __syncthreads();
    float denom = fmaxf(sqrtf(red[0]), 1e-12f);
    out[g * 64 + t] = acc / denom;
}

// --------------------------------- launcher -----------------------------------
extern "C" void kernel_launch(void* const* d_in, const int* in_sizes, int n_in,
                              void* d_out, int out_size) {
    const float* x    = (const float*)d_in[0];
    const int* src    = (const int*)d_in[1];
    const int* dst    = (const int*)d_in[2];
    const int* batch  = (const int*)d_in[3];
    const float* W1  = (const float*)d_in[4];
    const float* b1  = (const float*)d_in[5];
    const float* G1  = (const float*)d_in[6];
    const float* be1 = (const float*)d_in[7];
    const float* W2  = (const float*)d_in[8];
    const float* b2  = (const float*)d_in[9];
    const float* G2  = (const float*)d_in[10];
    const float* be2 = (const float*)d_in[11];
    const float* W3  = (const float*)d_in[12];
    const float* b3  = (const float*)d_in[13];
    const float* G3  = (const float*)d_in[14];
    const float* be3 = (const float*)d_in[15];
    const float* Wf1 = (const float*)d_in[16];
    const float* bf1 = (const float*)d_in[17];
    const float* G4  = (const float*)d_in[18];
    const float* be4 = (const float*)d_in[19];
    const float* Wf2 = (const float*)d_in[20];
    const float* bf2 = (const float*)d_in[21];

    int n = in_sizes[0] / 6;
    int e = in_sizes[1];
    int nb = (n + 1023) / 1024;
    float invn = 1.0f / (float)n;

    int zmax = n > NGRAPH * 128 ? n : NGRAPH * 128;
    zero_kernel<<<(zmax + 255) / 256, 256>>>(n);
    deg_kernel<<<(e + 255) / 256, 256>>>(dst, e);
    scan_block_kernel<<<nb, 1024>>>(n);
    scan_sums_kernel<<<1, 128>>>(nb);
    scan_fin_kernel<<<(n + 255) / 256, 256>>>(n);
    fill_kernel<<<(e + 255) / 256, 256>>>(src, dst, e);

    int wblocks = (n + 7) / 8;  // warp-per-node, 256 threads (R1 grids)

    // Layer 1
    gemm1_kernel<<<(n + 255) / 256, 256>>>(x, W1, n);
    agg32_kernel<<<2048, 256>>>(b1, 0, n);
    // Layer 2 (BN1 fused into gemm2)
    gemm2_kernel<<<wblocks, 256>>>(W2, G1, be1, invn, n);
    agg64_kernel<<<2048, 256>>>(b2, 64, n);
    // Layer 3 (BN2 fused into gemm3)
    gemm3_kernel<<<wblocks, 256>>>(W3, G2, be2, invn, n);
    // Aggregation + stats + fused raw max-pool (no g_B write)
    agg128p_kernel<<<2048, 256>>>(b3, batch, 192, n);
    // MLP head (BN3 fused into fc1, BN4 fused into fc2)
    fc1_kernel<<<NGRAPH, 128>>>(Wf1, bf1, G3, be3, invn);
    fc2_kernel<<<NGRAPH, 64>>>(Wf2, bf2, G4, be4, (float*)d_out);
}

// round 5
// speedup vs baseline: 1.4798x; 1.0223x over previous
#include <cuda_runtime.h>
#include <cuda_bf16.h>
#include <math.h>

#define MAXN 100000
#define MAXE 1600000
#define NGRAPH 512

// ------------------------- device scratch ----------
__device__ float g_A[(size_t)MAXN * 128];
__device__ float g_B[(size_t)MAXN * 128];
__device__ int   g_deg[MAXN];
__device__ int   g_tmp[MAXN];
__device__ int   g_rowptr[MAXN + 1];
__device__ int   g_cursor[MAXN];
__device__ int   g_col[MAXE];
__device__ float g_edinv[MAXE];             // dinv[src] per CSR slot
__device__ float g_dinv[MAXN];
__device__ int   g_bsums[128];
__device__ float g_stats[1024];             // [0,64)=L1 [64,192)=L2 [192,448)=L3 [448,704)=L4
__device__ unsigned g_poolu[NGRAPH * 128];  // order-encoded float max
__device__ float g_q[NGRAPH * 128];

__device__ __forceinline__ unsigned enc_f(float f) {
    unsigned b = __float_as_uint(f);
    return (b & 0x80000000u) ? ~b : (b | 0x80000000u);
}
__device__ __forceinline__ float dec_f(unsigned k) {
    unsigned b = (k & 0x80000000u) ? (k ^ 0x80000000u) : ~k;
    return __uint_as_float(b);
}

// ------------------------------- setup kernels ------------------------------
__global__ void zero_kernel(int n) {
    int i = blockIdx.x * blockDim.x + threadIdx.x;
    if (i < n) g_deg[i] = 0;
    if (i < 1024) g_stats[i] = 0.f;
    if (i < NGRAPH * 128) g_poolu[i] = 0u;
}

__global__ void deg_kernel(const int* __restrict__ dst, int e) {
    int i = blockIdx.x * blockDim.x + threadIdx.x;
    if (i < e) atomicAdd(&g_deg[dst[i]], 1);
}

__global__ void scan_block_kernel(int n) {
    __shared__ int s[1024];
    int i = blockIdx.x * 1024 + threadIdx.x;
    int v = (i < n) ? g_deg[i] : 0;
    s[threadIdx.x] = v;
    __syncthreads();
    for (int off = 1; off < 1024; off <<= 1) {
        int t = (threadIdx.x >= off) ? s[threadIdx.x - off] : 0;
        __syncthreads();
        s[threadIdx.x] += t;
        __syncthreads();
    }
    if (i < n) g_tmp[i] = s[threadIdx.x];
    if (threadIdx.x == 1023) g_bsums[blockIdx.x] = s[1023];
}

__global__ void scan_sums_kernel(int nb) {
    __shared__ int s[128];
    int t = threadIdx.x;
    int v = (t < nb) ? g_bsums[t] : 0;
    s[t] = v;
    __syncthreads();
    for (int off = 1; off < 128; off <<= 1) {
        int u = (t >= off) ? s[t - off] : 0;
        __syncthreads();
        s[t] += u;
        __syncthreads();
    }
    if (t < nb) g_bsums[t] = s[t] - v;   // exclusive
}

__global__ void scan_fin_kernel(int n) {
    int i = blockIdx.x * blockDim.x + threadIdx.x;
    if (i >= n) return;
    int incl = g_tmp[i] + g_bsums[i >> 10];
    g_rowptr[i + 1] = incl;
    g_cursor[i] = incl - g_deg[i];
    g_dinv[i] = rsqrtf((float)(g_deg[i] + 1));
    if (i == 0) g_rowptr[0] = 0;
}

__global__ void fill_kernel(const int* __restrict__ src, const int* __restrict__ dst, int e) {
    int i = blockIdx.x * blockDim.x + threadIdx.x;
    if (i < e) {
        int s = src[i];
        int p = atomicAdd(&g_cursor[dst[i]], 1);
        g_col[p] = s;
        g_edinv[p] = g_dinv[s];
    }
}

// ------------------------------- layer 1 (old style) -------------------------
// gemm1: hs = dinv_s * (x @ W1)  -> g_A [N,32]
__global__ void gemm1_kernel(const float* __restrict__ x, const float* __restrict__ W, int n) {
    __shared__ float Ws[6 * 32];
    int tid = threadIdx.x;
    if (tid < 6 * 32) Ws[tid] = W[tid];
    __syncthreads();
    int i = blockIdx.x * blockDim.x + tid;
    if (i >= n) return;
    float xv[6];
#pragma unroll
    for (int k = 0; k < 6; k++) xv[k] = x[(size_t)i * 6 + k];
    float dv = g_dinv[i];
    size_t base = (size_t)i * 32;
#pragma unroll
    for (int c = 0; c < 32; c++) {
        float acc = 0.f;
#pragma unroll
        for (int k = 0; k < 6; k++) acc = fmaf(xv[k], Ws[k * 32 + c], acc);
        g_A[base + c] = dv * acc;
    }
}

// agg32: o1 = dinv_d * sum hs + b1 ; stats1 ; write w1 = o1 * dinv_d -> g_B [N,32]
__global__ void agg32_kernel(const float* __restrict__ bias, int n) {
    __shared__ float sred[64];
    int tid = threadIdx.x;
    if (tid < 64) sred[tid] = 0.f;
    __syncthreads();
    int lane = tid & 31;
    int nw = (gridDim.x * blockDim.x) >> 5;
    int gw = (blockIdx.x * blockDim.x + tid) >> 5;
    float b = bias[lane];
    float ps = 0.f, pq = 0.f;
    for (int d = gw; d < n; d += nw) {
        float acc = g_A[(size_t)d * 32 + lane];
        int beg = g_rowptr[d], end = g_rowptr[d + 1];
        for (int j = beg; j < end; j++) {
            acc += g_A[(size_t)g_col[j] * 32 + lane];
        }
        float dv = g_dinv[d];
        float o = fmaf(dv, acc, b);
        g_B[(size_t)d * 32 + lane] = o * dv;   // w1
        ps += o; pq += o * o;
    }
    atomicAdd(&sred[lane], ps);
    atomicAdd(&sred[32 + lane], pq);
    __syncthreads();
    if (tid < 64) atomicAdd(&g_stats[tid], sred[tid]);
}

// ------------------------------- layer 2 (swapped) ---------------------------
// gather2: u2_d = sum_{N+(d)} relu(sc1*w1_s + sh1*dinv_s)  -> g_A [N,32]
__global__ void gather2_kernel(const float* __restrict__ gamma, const float* __restrict__ beta,
                               float invn, int n) {
    __shared__ float ssc[32], ssh[32];
    int tid = threadIdx.x;
    if (tid < 32) {
        float m = g_stats[tid] * invn;
        float var = g_stats[32 + tid] * invn - m * m;
        float s = gamma[tid] * rsqrtf(var + 1e-5f);
        ssc[tid] = s;
        ssh[tid] = fmaf(-m, s, beta[tid]);
    }
    __syncthreads();
    int lane = tid & 31;
    int nw = (gridDim.x * blockDim.x) >> 5;
    int gw = (blockIdx.x * blockDim.x + tid) >> 5;
    float sc = ssc[lane], sh = ssh[lane];
    for (int d = gw; d < n; d += nw) {
        float dvd = g_dinv[d];
        float w = g_B[(size_t)d * 32 + lane];
        float acc = fmaxf(fmaf(sc, w, sh * dvd), 0.f);     // self term
        int beg = g_rowptr[d], end = g_rowptr[d + 1];
        for (int j = beg; j < end; j++) {
            int s = g_col[j];
            float ed = g_edinv[j];
            float v = g_B[(size_t)s * 32 + lane];
            acc += fmaxf(fmaf(sc, v, sh * ed), 0.f);
        }
        g_A[(size_t)d * 32 + lane] = acc;
    }
}

// gemm2n: o2 = (u2 @ W2)*dinv_d + b2 ; stats2 ; write w2 = o2*dinv_d -> g_B [N,64]
__global__ void gemm2n_kernel(const float* __restrict__ W, const float* __restrict__ bias, int n) {
    __shared__ float Ws[32 * 64];
    __shared__ float sb[64];
    __shared__ float sred[128];
    int tid = threadIdx.x;
    for (int i = tid; i < 32 * 64; i += blockDim.x) Ws[i] = W[i];
    if (tid < 64) sb[tid] = bias[tid];
    if (tid < 128) sred[tid] = 0.f;
    __syncthreads();
    int lane = tid & 31;
    int gw = (blockIdx.x * blockDim.x + tid) >> 5;
    if (gw < n) {
        float u = g_A[(size_t)gw * 32 + lane];
        float a0 = 0.f, a1 = 0.f;
#pragma unroll
        for (int k = 0; k < 32; k++) {
            float v = __shfl_sync(0xffffffffu, u, k);
            a0 = fmaf(v, Ws[k * 64 + lane], a0);
            a1 = fmaf(v, Ws[k * 64 + 32 + lane], a1);
        }
        float dv = g_dinv[gw];
        float o0 = fmaf(a0, dv, sb[lane]);
        float o1 = fmaf(a1, dv, sb[32 + lane]);
        size_t ob = (size_t)gw * 64;
        g_B[ob + lane] = o0 * dv;
        g_B[ob + 32 + lane] = o1 * dv;
        atomicAdd(&sred[lane], o0);
        atomicAdd(&sred[32 + lane], o1);
        atomicAdd(&sred[64 + lane], o0 * o0);
        atomicAdd(&sred[96 + lane], o1 * o1);
    }
    __syncthreads();
    if (tid < 128) atomicAdd(&g_stats[64 + tid], sred[tid]);
}

// ------------------------------- layer 3 (swapped) ---------------------------
// gather3: u3_d = sum relu(sc2*w2_s + sh2*dinv_s)  -> g_A [N,64]  (float2/lane)
__global__ void gather3_kernel(const float* __restrict__ gamma, const float* __restrict__ beta,
                               float invn, int n) {
    __shared__ float ssc[64], ssh[64];
    int tid = threadIdx.x;
    if (tid < 64) {
        float m = g_stats[64 + tid] * invn;
        float var = g_stats[128 + tid] * invn - m * m;
        float s = gamma[tid] * rsqrtf(var + 1e-5f);
        ssc[tid] = s;
        ssh[tid] = fmaf(-m, s, beta[tid]);
    }
    __syncthreads();
    int lane = tid & 31;
    int nw = (gridDim.x * blockDim.x) >> 5;
    int gw = (blockIdx.x * blockDim.x + tid) >> 5;
    int c0 = lane * 2;
    float sc0 = ssc[c0], sc1 = ssc[c0 + 1];
    float sh0 = ssh[c0], sh1 = ssh[c0 + 1];
    for (int d = gw; d < n; d += nw) {
        float dvd = g_dinv[d];
        float2 w = *(const float2*)&g_B[(size_t)d * 64 + c0];
        float ax = fmaxf(fmaf(sc0, w.x, sh0 * dvd), 0.f);
        float ay = fmaxf(fmaf(sc1, w.y, sh1 * dvd), 0.f);
        int beg = g_rowptr[d], end = g_rowptr[d + 1];
        for (int j = beg; j < end; j++) {
            int s = g_col[j];
            float ed = g_edinv[j];
            float2 v = *(const float2*)&g_B[(size_t)s * 64 + c0];
            ax += fmaxf(fmaf(sc0, v.x, sh0 * ed), 0.f);
            ay += fmaxf(fmaf(sc1, v.y, sh1 * ed), 0.f);
        }
        *(float2*)&g_A[(size_t)d * 64 + c0] = make_float2(ax, ay);
    }
}

// gemm3n: o3 = (u3 @ W3)*dinv_d + b3 ; stats3 ; fused raw max-pool (8 nodes/block).
__global__ void gemm3n_kernel(const float* __restrict__ W, const float* __restrict__ bias,
                              const int* __restrict__ batch, int n) {
    __shared__ float Ws[64 * 128];
    __shared__ float sb[128];
    __shared__ float sred[256];
    __shared__ float po[8 * 128];
    __shared__ int bat[8];
    int tid = threadIdx.x;
    for (int i = tid; i < 64 * 128; i += blockDim.x) Ws[i] = W[i];
    if (tid < 128) sb[tid] = bias[tid];
    if (tid < 256) sred[tid] = 0.f;
    int nb0 = blockIdx.x * 8;
    if (tid < 8) bat[tid] = (nb0 + tid < n) ? batch[nb0 + tid] : -1;
    __syncthreads();
    int lane = tid & 31;
    int w = tid >> 5;
    int node = nb0 + w;
    if (node < n) {
        float u0 = g_A[(size_t)node * 64 + lane];
        float u1 = g_A[(size_t)node * 64 + 32 + lane];
        float a0 = 0.f, a1 = 0.f, a2 = 0.f, a3 = 0.f;
#pragma unroll
        for (int k = 0; k < 32; k++) {
            float v = __shfl_sync(0xffffffffu, u0, k);
            const float* ww = &Ws[k * 128];
            a0 = fmaf(v, ww[lane], a0);
            a1 = fmaf(v, ww[32 + lane], a1);
            a2 = fmaf(v, ww[64 + lane], a2);
            a3 = fmaf(v, ww[96 + lane], a3);
        }
#pragma unroll
        for (int k = 0; k < 32; k++) {
            float v = __shfl_sync(0xffffffffu, u1, k);
            const float* ww = &Ws[(32 + k) * 128];
            a0 = fmaf(v, ww[lane], a0);
            a1 = fmaf(v, ww[32 + lane], a1);
            a2 = fmaf(v, ww[64 + lane], a2);
            a3 = fmaf(v, ww[96 + lane], a3);
        }
        float dv = g_dinv[node];
        float o0 = fmaf(a0, dv, sb[lane]);
        float o1 = fmaf(a1, dv, sb[32 + lane]);
        float o2 = fmaf(a2, dv, sb[64 + lane]);
        float o3 = fmaf(a3, dv, sb[96 + lane]);
        po[w * 128 + lane]       = o0;
        po[w * 128 + 32 + lane]  = o1;
        po[w * 128 + 64 + lane]  = o2;
        po[w * 128 + 96 + lane]  = o3;
        atomicAdd(&sred[lane], o0);
        atomicAdd(&sred[32 + lane], o1);
        atomicAdd(&sred[64 + lane], o2);
        atomicAdd(&sred[96 + lane], o3);
        atomicAdd(&sred[128 + lane], o0 * o0);
        atomicAdd(&sred[160 + lane], o1 * o1);
        atomicAdd(&sred[192 + lane], o2 * o2);
        atomicAdd(&sred[224 + lane], o3 * o3);
    }
    __syncthreads();
    if (tid < 128) {
        int ch = tid;
        int cur = -1;
        float m = -INFINITY;
        for (int k = 0; k < 8; k++) {
            int bg = bat[k];
            if (bg < 0) break;    // sorted; invalid tail
            if (bg != cur) {
                if (cur >= 0) atomicMax(&g_poolu[cur * 128 + ch], enc_f(m));
                cur = bg;
                m = -INFINITY;
            }
            m = fmaxf(m, po[k * 128 + ch]);
        }
        if (cur >= 0) atomicMax(&g_poolu[cur * 128 + ch], enc_f(m));
    }
    if (tid < 256) atomicAdd(&g_stats[192 + tid], sred[tid]);
}

// --------------------------------- final MLP ----------------------------------
__global__ void fc1_kernel(const float* __restrict__ Wf1, const float* __restrict__ bf1,
                           const float* __restrict__ g3, const float* __restrict__ be3,
                           float invn) {
    __shared__ float pr[128];
    int g = blockIdx.x, t = threadIdx.x;
    {
        float mm = g_stats[192 + t] * invn;
        float var = g_stats[320 + t] * invn - mm * mm;
        float s = g3[t] * rsqrtf(var + 1e-5f);
        float sh = fmaf(-mm, s, be3[t]);
        float raw = dec_f(g_poolu[g * 128 + t]);
        pr[t] = fmaxf(fmaf(s, raw, sh), 0.f);
    }
    __syncthreads();
    float acc = bf1[t];
#pragma unroll 8
    for (int k = 0; k < 128; k++) acc = fmaf(pr[k], Wf1[k * 128 + t], acc);
    g_q[g * 128 + t] = acc;
    atomicAdd(&g_stats[448 + t], acc);
    atomicAdd(&g_stats[576 + t], acc * acc);
}

__global__ void fc2_kernel(const float* __restrict__ Wf2, const float* __restrict__ bf2,
                           const float* __restrict__ g4, const float* __restrict__ be4,
                           float* __restrict__ out) {
    __shared__ float r[128];
    __shared__ float red[64];
    int g = blockIdx.x, t = threadIdx.x;  // 64 threads
    const float invg = 1.0f / (float)NGRAPH;
#pragma unroll
    for (int h = 0; h < 2; h++) {
        int c = t + 64 * h;
        float mm = g_stats[448 + c] * invg;
        float var = g_stats[576 + c] * invg - mm * mm;
        float s = g4[c] * rsqrtf(var + 1e-5f);
        float sh = fmaf(-mm, s, be4[c]);
        r[c] = fmaxf(fmaf(s, g_q[g * 128 + c], sh), 0.f);
    }
    __syncthreads();
    float acc = bf2[t];
#pragma unroll 8
    for (int k = 0; k < 128; k++) acc = fmaf(r[k], Wf2[k * 64 + t], acc);
    red[t] = acc * acc;
    for (int off = 32; off > 0; off >>= 1) {
        __syncthreads();
        if (t < off) red[t] += red[t + off];
    }
    __syncthreads();
    float denom = fmaxf(sqrtf(red[0]), 1e-12f);
    out[g * 64 + t] = acc / denom;
}

// --------------------------------- launcher -----------------------------------
extern "C" void kernel_launch(void* const* d_in, const int* in_sizes, int n_in,
                              void* d_out, int out_size) {
    const float* x    = (const float*)d_in[0];
    const int* src    = (const int*)d_in[1];
    const int* dst    = (const int*)d_in[2];
    const int* batch  = (const int*)d_in[3];
    const float* W1  = (const float*)d_in[4];
    const float* b1  = (const float*)d_in[5];
    const float* G1  = (const float*)d_in[6];
    const float* be1 = (const float*)d_in[7];
    const float* W2  = (const float*)d_in[8];
    const float* b2  = (const float*)d_in[9];
    const float* G2  = (const float*)d_in[10];
    const float* be2 = (const float*)d_in[11];
    const float* W3  = (const float*)d_in[12];
    const float* b3  = (const float*)d_in[13];
    const float* G3  = (const float*)d_in[14];
    const float* be3 = (const float*)d_in[15];
    const float* Wf1 = (const float*)d_in[16];
    const float* bf1 = (const float*)d_in[17];
    const float* G4  = (const float*)d_in[18];
    const float* be4 = (const float*)d_in[19];
    const float* Wf2 = (const float*)d_in[20];
    const float* bf2 = (const float*)d_in[21];

    int n = in_sizes[0] / 6;
    int e = in_sizes[1];
    int nb = (n + 1023) / 1024;
    float invn = 1.0f / (float)n;

    int zmax = n > NGRAPH * 128 ? n : NGRAPH * 128;
    zero_kernel<<<(zmax + 255) / 256, 256>>>(n);
    deg_kernel<<<(e + 255) / 256, 256>>>(dst, e);
    scan_block_kernel<<<nb, 1024>>>(n);
    scan_sums_kernel<<<1, 128>>>(nb);
    scan_fin_kernel<<<(n + 255) / 256, 256>>>(n);
    fill_kernel<<<(e + 255) / 256, 256>>>(src, dst, e);

    int wblocks = (n + 7) / 8;  // warp-per-node / 8-nodes-per-block grids

    // Layer 1 (old formulation)
    gemm1_kernel<<<(n + 255) / 256, 256>>>(x, W1, n);
    agg32_kernel<<<2048, 256>>>(b1, n);
    // Layer 2 (swapped: gather pre-GEMM 32-wide)
    gather2_kernel<<<2048, 256>>>(G1, be1, invn, n);
    gemm2n_kernel<<<wblocks, 256>>>(W2, b2, n);
    // Layer 3 (swapped: gather pre-GEMM 64-wide)
    gather3_kernel<<<2048, 256>>>(G2, be2, invn, n);
    gemm3n_kernel<<<wblocks, 256>>>(W3, b3, batch, n);
    // MLP head
    fc1_kernel<<<NGRAPH, 128>>>(Wf1, bf1, G3, be3, invn);
    fc2_kernel<<<NGRAPH, 64>>>(Wf2, bf2, G4, be4, (float*)d_out);
}

// round 6
// speedup vs baseline: 1.7967x; 1.2141x over previous
#include <cuda_runtime.h>
#include <cuda_bf16.h>
#include <math.h>

#define MAXN 100000
#define MAXE 1600000
#define NGRAPH 512

// ------------------------- device scratch ----------
__device__ float g_A[(size_t)MAXN * 128];
__device__ float g_B[(size_t)MAXN * 128];
__device__ int   g_deg[MAXN];
__device__ int   g_tmp[MAXN];
__device__ int   g_rowptr[MAXN + 1];
__device__ int   g_cursor[MAXN];
__device__ int   g_col[MAXE];
__device__ float g_edinv[MAXE];             // dinv[src] per CSR slot
__device__ float g_dinv[MAXN];
__device__ int   g_bsums[128];
__device__ float g_stats[1024];             // [0,64)=L1 [64,192)=L2 [192,448)=L3 [448,704)=L4
__device__ unsigned g_poolu[NGRAPH * 128];  // order-encoded float max
__device__ float g_q[NGRAPH * 128];

__device__ __forceinline__ unsigned enc_f(float f) {
    unsigned b = __float_as_uint(f);
    return (b & 0x80000000u) ? ~b : (b | 0x80000000u);
}
__device__ __forceinline__ float dec_f(unsigned k) {
    unsigned b = (k & 0x80000000u) ? (k ^ 0x80000000u) : ~k;
    return __uint_as_float(b);
}

// ------------------------------- setup kernels ------------------------------
__global__ void zero_kernel(int n) {
    int i = blockIdx.x * blockDim.x + threadIdx.x;
    if (i < n) g_deg[i] = 0;
    if (i < 1024) g_stats[i] = 0.f;
    if (i < NGRAPH * 128) g_poolu[i] = 0u;
}

__global__ void deg_kernel(const int* __restrict__ dst, int e) {
    int i = blockIdx.x * blockDim.x + threadIdx.x;
    if (i < e) atomicAdd(&g_deg[dst[i]], 1);
}

__global__ void scan_block_kernel(int n) {
    __shared__ int s[1024];
    int i = blockIdx.x * 1024 + threadIdx.x;
    int v = (i < n) ? g_deg[i] : 0;
    s[threadIdx.x] = v;
    __syncthreads();
    for (int off = 1; off < 1024; off <<= 1) {
        int t = (threadIdx.x >= off) ? s[threadIdx.x - off] : 0;
        __syncthreads();
        s[threadIdx.x] += t;
        __syncthreads();
    }
    if (i < n) g_tmp[i] = s[threadIdx.x];
    if (threadIdx.x == 1023) g_bsums[blockIdx.x] = s[1023];
}

// merged: local scan of block sums + finalize rowptr/cursor/dinv
__global__ void scan_fin2_kernel(int n, int nb) {
    __shared__ int s[128];
    int tid = threadIdx.x;
    if (tid < 128) s[tid] = (tid < nb) ? g_bsums[tid] : 0;
    __syncthreads();
    for (int off = 1; off < 128; off <<= 1) {
        int t = 0;
        if (tid < 128 && tid >= off) t = s[tid - off];
        __syncthreads();
        if (tid < 128) s[tid] += t;
        __syncthreads();
    }
    int boff = (blockIdx.x == 0) ? 0 : s[blockIdx.x - 1];
    int i = blockIdx.x * 1024 + tid;
    if (i >= n) return;
    int incl = g_tmp[i] + boff;
    g_rowptr[i + 1] = incl;
    g_cursor[i] = incl - g_deg[i];
    g_dinv[i] = rsqrtf((float)(g_deg[i] + 1));
    if (i == 0) g_rowptr[0] = 0;
}

__global__ void fill_kernel(const int* __restrict__ src, const int* __restrict__ dst, int e) {
    int i = blockIdx.x * blockDim.x + threadIdx.x;
    if (i < e) {
        int s = src[i];
        int p = atomicAdd(&g_cursor[dst[i]], 1);
        g_col[p] = s;
        g_edinv[p] = g_dinv[s];
    }
}

// ------------------------------- layer 1 -------------------------------------
// gemm1: hs = dinv_s * (x @ W1)  -> g_A [N,32]
__global__ void gemm1_kernel(const float* __restrict__ x, const float* __restrict__ W, int n) {
    __shared__ float Ws[6 * 32];
    int tid = threadIdx.x;
    if (tid < 6 * 32) Ws[tid] = W[tid];
    __syncthreads();
    int i = blockIdx.x * blockDim.x + tid;
    if (i >= n) return;
    float xv[6];
#pragma unroll
    for (int k = 0; k < 6; k++) xv[k] = x[(size_t)i * 6 + k];
    float dv = g_dinv[i];
    size_t base = (size_t)i * 32;
#pragma unroll
    for (int c = 0; c < 32; c++) {
        float acc = 0.f;
#pragma unroll
        for (int k = 0; k < 6; k++) acc = fmaf(xv[k], Ws[k * 32 + c], acc);
        g_A[base + c] = dv * acc;
    }
}

// agg32: o1 = dinv_d * sum hs + b1 ; stats1 ; write w1 = o1 * dinv_d -> g_B [N,32]
__global__ void agg32_kernel(const float* __restrict__ bias, int n) {
    __shared__ float sred[64];
    int tid = threadIdx.x;
    if (tid < 64) sred[tid] = 0.f;
    __syncthreads();
    int lane = tid & 31;
    int nw = (gridDim.x * blockDim.x) >> 5;
    int gw = (blockIdx.x * blockDim.x + tid) >> 5;
    float b = bias[lane];
    float ps = 0.f, pq = 0.f;
    for (int d = gw; d < n; d += nw) {
        float acc = g_A[(size_t)d * 32 + lane];
        int beg = g_rowptr[d], end = g_rowptr[d + 1];
        for (int j = beg; j < end; j++) {
            acc += g_A[(size_t)g_col[j] * 32 + lane];
        }
        float dv = g_dinv[d];
        float o = fmaf(dv, acc, b);
        g_B[(size_t)d * 32 + lane] = o * dv;   // w1
        ps += o; pq += o * o;
    }
    atomicAdd(&sred[lane], ps);
    atomicAdd(&sred[32 + lane], pq);
    __syncthreads();
    if (tid < 64) atomicAdd(&g_stats[tid], sred[tid]);
}

// ------------------------------- layer 2 (fused gather+gemm) -----------------
// per warp-node d: u = sum relu(sc1*w1_s + sh1*dinv_s); o2 = (u@W2)*dinv_d + b2;
// write w2 = o2*dinv_d -> g_A [N,64]; accumulate stats2.
__global__ void layer2_kernel(const float* __restrict__ W, const float* __restrict__ bias,
                              const float* __restrict__ gamma, const float* __restrict__ beta,
                              float invn, int n) {
    __shared__ float Ws[32 * 64];
    __shared__ float ssc[32], ssh[32];
    __shared__ float sred[128];
    int tid = threadIdx.x;
    for (int i = tid; i < 32 * 64; i += blockDim.x) Ws[i] = W[i];
    if (tid < 32) {
        float m = g_stats[tid] * invn;
        float var = g_stats[32 + tid] * invn - m * m;
        float s = gamma[tid] * rsqrtf(var + 1e-5f);
        ssc[tid] = s;
        ssh[tid] = fmaf(-m, s, beta[tid]);
    }
    if (tid < 128) sred[tid] = 0.f;
    __syncthreads();
    int lane = tid & 31;
    int nw = (gridDim.x * blockDim.x) >> 5;
    int gw = (blockIdx.x * blockDim.x + tid) >> 5;
    float sc = ssc[lane], sh = ssh[lane];
    float b0 = bias[lane], b1 = bias[32 + lane];
    float ps0 = 0.f, ps1 = 0.f, pq0 = 0.f, pq1 = 0.f;
    for (int d = gw; d < n; d += nw) {
        float dvd = g_dinv[d];
        float w = g_B[(size_t)d * 32 + lane];
        float u = fmaxf(fmaf(sc, w, sh * dvd), 0.f);       // self term
        int beg = g_rowptr[d], end = g_rowptr[d + 1];
        for (int j = beg; j < end; j++) {
            int s = g_col[j];
            float ed = g_edinv[j];
            float v = g_B[(size_t)s * 32 + lane];
            u += fmaxf(fmaf(sc, v, sh * ed), 0.f);
        }
        float a0 = 0.f, a1 = 0.f;
#pragma unroll
        for (int k = 0; k < 32; k++) {
            float v = __shfl_sync(0xffffffffu, u, k);
            a0 = fmaf(v, Ws[k * 64 + lane], a0);
            a1 = fmaf(v, Ws[k * 64 + 32 + lane], a1);
        }
        float o0 = fmaf(a0, dvd, b0);
        float o1 = fmaf(a1, dvd, b1);
        size_t ob = (size_t)d * 64;
        g_A[ob + lane] = o0 * dvd;       // w2
        g_A[ob + 32 + lane] = o1 * dvd;
        ps0 += o0; ps1 += o1; pq0 += o0 * o0; pq1 += o1 * o1;
    }
    atomicAdd(&sred[lane], ps0);
    atomicAdd(&sred[32 + lane], ps1);
    atomicAdd(&sred[64 + lane], pq0);
    atomicAdd(&sred[96 + lane], pq1);
    __syncthreads();
    if (tid < 128) atomicAdd(&g_stats[64 + tid], sred[tid]);
}

// ------------------------------- layer 3 (fused gather+gemm+pool) ------------
// chunked contiguous nodes per warp (sorted batch -> cheap pool flush).
__global__ void layer3_kernel(const float* __restrict__ W, const float* __restrict__ bias,
                              const float* __restrict__ gamma, const float* __restrict__ beta,
                              const int* __restrict__ batch, float invn, int n) {
    __shared__ float Ws[64 * 128];   // 32 KB
    __shared__ float ssc[64], ssh[64];
    __shared__ float sred[256];
    int tid = threadIdx.x;
    for (int i = tid; i < 64 * 128; i += blockDim.x) Ws[i] = W[i];
    if (tid < 64) {
        float m = g_stats[64 + tid] * invn;
        float var = g_stats[128 + tid] * invn - m * m;
        float s = gamma[tid] * rsqrtf(var + 1e-5f);
        ssc[tid] = s;
        ssh[tid] = fmaf(-m, s, beta[tid]);
    }
    if (tid < 256) sred[tid] = 0.f;
    __syncthreads();
    int lane = tid & 31;
    int nwarp = (gridDim.x * blockDim.x) >> 5;
    int w = (blockIdx.x * blockDim.x + tid) >> 5;
    int chunk = (n + nwarp - 1) / nwarp;
    int beg_d = w * chunk;
    int end_d = min(beg_d + chunk, n);
    int c0 = lane * 2;
    float sc0 = ssc[c0], sc1 = ssc[c0 + 1];
    float sh0 = ssh[c0], sh1 = ssh[c0 + 1];
    float bb0 = bias[lane], bb1 = bias[32 + lane];
    float bb2 = bias[64 + lane], bb3 = bias[96 + lane];
    float ps[4] = {0.f, 0.f, 0.f, 0.f};
    float pq[4] = {0.f, 0.f, 0.f, 0.f};
    float m0 = -INFINITY, m1 = -INFINITY, m2 = -INFINITY, m3 = -INFINITY;
    int cur = -1;
    for (int d = beg_d; d < end_d; d++) {
        int bg = batch[d];
        if (bg != cur) {
            if (cur >= 0) {
                atomicMax(&g_poolu[cur * 128 + lane],      enc_f(m0));
                atomicMax(&g_poolu[cur * 128 + 32 + lane], enc_f(m1));
                atomicMax(&g_poolu[cur * 128 + 64 + lane], enc_f(m2));
                atomicMax(&g_poolu[cur * 128 + 96 + lane], enc_f(m3));
            }
            cur = bg;
            m0 = m1 = m2 = m3 = -INFINITY;
        }
        float dvd = g_dinv[d];
        float2 ww = *(const float2*)&g_A[(size_t)d * 64 + c0];
        float ax = fmaxf(fmaf(sc0, ww.x, sh0 * dvd), 0.f);
        float ay = fmaxf(fmaf(sc1, ww.y, sh1 * dvd), 0.f);
        int jb = g_rowptr[d], je = g_rowptr[d + 1];
        for (int j = jb; j < je; j++) {
            int s = g_col[j];
            float ed = g_edinv[j];
            float2 v = *(const float2*)&g_A[(size_t)s * 64 + c0];
            ax += fmaxf(fmaf(sc0, v.x, sh0 * ed), 0.f);
            ay += fmaxf(fmaf(sc1, v.y, sh1 * ed), 0.f);
        }
        // GEMM: channel 2k held by lane k (.x), channel 2k+1 by lane k (.y)
        float a0 = 0.f, a1 = 0.f, a2 = 0.f, a3 = 0.f;
#pragma unroll
        for (int kk = 0; kk < 32; kk++) {
            float vx = __shfl_sync(0xffffffffu, ax, kk);
            float vy = __shfl_sync(0xffffffffu, ay, kk);
            const float* w0 = &Ws[(2 * kk) * 128];
            const float* w1 = &Ws[(2 * kk + 1) * 128];
            a0 = fmaf(vx, w0[lane], a0);       a0 = fmaf(vy, w1[lane], a0);
            a1 = fmaf(vx, w0[32 + lane], a1);  a1 = fmaf(vy, w1[32 + lane], a1);
            a2 = fmaf(vx, w0[64 + lane], a2);  a2 = fmaf(vy, w1[64 + lane], a2);
            a3 = fmaf(vx, w0[96 + lane], a3);  a3 = fmaf(vy, w1[96 + lane], a3);
        }
        float o0 = fmaf(a0, dvd, bb0);
        float o1 = fmaf(a1, dvd, bb1);
        float o2 = fmaf(a2, dvd, bb2);
        float o3 = fmaf(a3, dvd, bb3);
        ps[0] += o0; ps[1] += o1; ps[2] += o2; ps[3] += o3;
        pq[0] += o0 * o0; pq[1] += o1 * o1; pq[2] += o2 * o2; pq[3] += o3 * o3;
        m0 = fmaxf(m0, o0); m1 = fmaxf(m1, o1);
        m2 = fmaxf(m2, o2); m3 = fmaxf(m3, o3);
    }
    if (cur >= 0) {
        atomicMax(&g_poolu[cur * 128 + lane],      enc_f(m0));
        atomicMax(&g_poolu[cur * 128 + 32 + lane], enc_f(m1));
        atomicMax(&g_poolu[cur * 128 + 64 + lane], enc_f(m2));
        atomicMax(&g_poolu[cur * 128 + 96 + lane], enc_f(m3));
    }
    atomicAdd(&sred[lane], ps[0]);
    atomicAdd(&sred[32 + lane], ps[1]);
    atomicAdd(&sred[64 + lane], ps[2]);
    atomicAdd(&sred[96 + lane], ps[3]);
    atomicAdd(&sred[128 + lane], pq[0]);
    atomicAdd(&sred[160 + lane], pq[1]);
    atomicAdd(&sred[192 + lane], pq[2]);
    atomicAdd(&sred[224 + lane], pq[3]);
    __syncthreads();
    if (tid < 256) atomicAdd(&g_stats[192 + tid], sred[tid]);
}

// --------------------------------- final MLP ----------------------------------
__global__ void fc1_kernel(const float* __restrict__ Wf1, const float* __restrict__ bf1,
                           const float* __restrict__ g3, const float* __restrict__ be3,
                           float invn) {
    __shared__ float pr[128];
    int g = blockIdx.x, t = threadIdx.x;
    {
        float mm = g_stats[192 + t] * invn;
        float var = g_stats[320 + t] * invn - mm * mm;
        float s = g3[t] * rsqrtf(var + 1e-5f);
        float sh = fmaf(-mm, s, be3[t]);
        float raw = dec_f(g_poolu[g * 128 + t]);
        pr[t] = fmaxf(fmaf(s, raw, sh), 0.f);
    }
    __syncthreads();
    float acc = bf1[t];
#pragma unroll 8
    for (int k = 0; k < 128; k++) acc = fmaf(pr[k], Wf1[k * 128 + t], acc);
    g_q[g * 128 + t] = acc;
    atomicAdd(&g_stats[448 + t], acc);
    atomicAdd(&g_stats[576 + t], acc * acc);
}

__global__ void fc2_kernel(const float* __restrict__ Wf2, const float* __restrict__ bf2,
                           const float* __restrict__ g4, const float* __restrict__ be4,
                           float* __restrict__ out) {
    __shared__ float r[128];
    __shared__ float red[64];
    int g = blockIdx.x, t = threadIdx.x;  // 64 threads
    const float invg = 1.0f / (float)NGRAPH;
#pragma unroll
    for (int h = 0; h < 2; h++) {
        int c = t + 64 * h;
        float mm = g_stats[448 + c] * invg;
        float var = g_stats[576 + c] * invg - mm * mm;
        float s = g4[c] * rsqrtf(var + 1e-5f);
        float sh = fmaf(-mm, s, be4[c]);
        r[c] = fmaxf(fmaf(s, g_q[g * 128 + c], sh), 0.f);
    }
    __syncthreads();
    float acc = bf2[t];
#pragma unroll 8
    for (int k = 0; k < 128; k++) acc = fmaf(r[k], Wf2[k * 64 + t], acc);
    red[t] = acc * acc;
    for (int off = 32; off > 0; off >>= 1) {
        __syncthreads();
        if (t < off) red[t] += red[t + off];
    }
    __syncthreads();
    float denom = fmaxf(sqrtf(red[0]), 1e-12f);
    out[g * 64 + t] = acc / denom;
}

// --------------------------------- launcher -----------------------------------
extern "C" void kernel_launch(void* const* d_in, const int* in_sizes, int n_in,
                              void* d_out, int out_size) {
    const float* x    = (const float*)d_in[0];
    const int* src    = (const int*)d_in[1];
    const int* dst    = (const int*)d_in[2];
    const int* batch  = (const int*)d_in[3];
    const float* W1  = (const float*)d_in[4];
    const float* b1  = (const float*)d_in[5];
    const float* G1  = (const float*)d_in[6];
    const float* be1 = (const float*)d_in[7];
    const float* W2  = (const float*)d_in[8];
    const float* b2  = (const float*)d_in[9];
    const float* G2  = (const float*)d_in[10];
    const float* be2 = (const float*)d_in[11];
    const float* W3  = (const float*)d_in[12];
    const float* b3  = (const float*)d_in[13];
    const float* G3  = (const float*)d_in[14];
    const float* be3 = (const float*)d_in[15];
    const float* Wf1 = (const float*)d_in[16];
    const float* bf1 = (const float*)d_in[17];
    const float* G4  = (const float*)d_in[18];
    const float* be4 = (const float*)d_in[19];
    const float* Wf2 = (const float*)d_in[20];
    const float* bf2 = (const float*)d_in[21];

    int n = in_sizes[0] / 6;
    int e = in_sizes[1];
    int nb = (n + 1023) / 1024;
    float invn = 1.0f / (float)n;

    int zmax = n > NGRAPH * 128 ? n : NGRAPH * 128;
    zero_kernel<<<(zmax + 255) / 256, 256>>>(n);
    deg_kernel<<<(e + 255) / 256, 256>>>(dst, e);
    scan_block_kernel<<<nb, 1024>>>(n);
    scan_fin2_kernel<<<nb, 1024>>>(n, nb);
    fill_kernel<<<(e + 255) / 256, 256>>>(src, dst, e);

    // Layer 1
    gemm1_kernel<<<(n + 255) / 256, 256>>>(x, W1, n);
    agg32_kernel<<<2048, 256>>>(b1, n);
    // Layer 2 fused (gather 32-wide + GEMM 32x64)
    layer2_kernel<<<2048, 256>>>(W2, b2, G1, be1, invn, n);
    // Layer 3 fused (gather 64-wide + GEMM 64x128 + stats + pool)
    layer3_kernel<<<2048, 256>>>(W3, b3, G2, be2, batch, invn, n);
    // MLP head
    fc1_kernel<<<NGRAPH, 128>>>(Wf1, bf1, G3, be3, invn);
    fc2_kernel<<<NGRAPH, 64>>>(Wf2, bf2, G4, be4, (float*)d_out);
}

// round 7
// speedup vs baseline: 1.8317x; 1.0195x over previous
#include <cuda_runtime.h>
#include <cuda_bf16.h>
#include <math.h>

#define MAXN 100000
#define MAXE 1600000
#define NGRAPH 512

// ------------------------- device scratch ----------
__device__ float g_A[(size_t)MAXN * 128];
__device__ float g_B[(size_t)MAXN * 128];
__device__ int   g_deg[MAXN];
__device__ int   g_tmp[MAXN];
__device__ int   g_rowptr[MAXN + 1];
__device__ int   g_cursor[MAXN];
__device__ int   g_col[MAXE];
__device__ float g_edinv[MAXE];             // dinv[src] per CSR slot
__device__ float g_dinv[MAXN];
__device__ int   g_bsums[128];
__device__ float g_stats[1024];             // [0,64)=L1 [64,192)=L2 [192,448)=L3 [448,704)=L4
__device__ unsigned g_poolu[NGRAPH * 128];  // order-encoded float max
__device__ float g_q[NGRAPH * 128];

__device__ __forceinline__ unsigned enc_f(float f) {
    unsigned b = __float_as_uint(f);
    return (b & 0x80000000u) ? ~b : (b | 0x80000000u);
}
__device__ __forceinline__ float dec_f(unsigned k) {
    unsigned b = (k & 0x80000000u) ? (k ^ 0x80000000u) : ~k;
    return __uint_as_float(b);
}

// ------------------------------- setup kernels ------------------------------
__global__ void zero_kernel(int n) {
    int i = blockIdx.x * blockDim.x + threadIdx.x;
    if (i < n) g_deg[i] = 0;
    if (i < 1024) g_stats[i] = 0.f;
    if (i < NGRAPH * 128) g_poolu[i] = 0u;
}

__global__ void deg_kernel(const int* __restrict__ dst, int e) {
    int i = blockIdx.x * blockDim.x + threadIdx.x;
    if (i < e) atomicAdd(&g_deg[dst[i]], 1);
}

__global__ void scan_block_kernel(int n) {
    __shared__ int s[1024];
    int i = blockIdx.x * 1024 + threadIdx.x;
    int v = (i < n) ? g_deg[i] : 0;
    s[threadIdx.x] = v;
    __syncthreads();
    for (int off = 1; off < 1024; off <<= 1) {
        int t = (threadIdx.x >= off) ? s[threadIdx.x - off] : 0;
        __syncthreads();
        s[threadIdx.x] += t;
        __syncthreads();
    }
    if (i < n) g_tmp[i] = s[threadIdx.x];
    if (threadIdx.x == 1023) g_bsums[blockIdx.x] = s[1023];
}

// merged: local scan of block sums + finalize rowptr/cursor/dinv
__global__ void scan_fin2_kernel(int n, int nb) {
    __shared__ int s[128];
    int tid = threadIdx.x;
    if (tid < 128) s[tid] = (tid < nb) ? g_bsums[tid] : 0;
    __syncthreads();
    for (int off = 1; off < 128; off <<= 1) {
        int t = 0;
        if (tid < 128 && tid >= off) t = s[tid - off];
        __syncthreads();
        if (tid < 128) s[tid] += t;
        __syncthreads();
    }
    int boff = (blockIdx.x == 0) ? 0 : s[blockIdx.x - 1];
    int i = blockIdx.x * 1024 + tid;
    if (i >= n) return;
    int incl = g_tmp[i] + boff;
    g_rowptr[i + 1] = incl;
    g_cursor[i] = incl - g_deg[i];
    g_dinv[i] = rsqrtf((float)(g_deg[i] + 1));
    if (i == 0) g_rowptr[0] = 0;
}

__global__ void fill_kernel(const int* __restrict__ src, const int* __restrict__ dst, int e) {
    int i = blockIdx.x * blockDim.x + threadIdx.x;
    if (i < e) {
        int s = src[i];
        int p = atomicAdd(&g_cursor[dst[i]], 1);
        g_col[p] = s;
        g_edinv[p] = g_dinv[s];
    }
}

// ------------------------------- layer 1 -------------------------------------
// gemm1: hs = dinv_s * (x @ W1)  -> g_A [N,32]
__global__ void gemm1_kernel(const float* __restrict__ x, const float* __restrict__ W, int n) {
    __shared__ float Ws[6 * 32];
    int tid = threadIdx.x;
    if (tid < 6 * 32) Ws[tid] = W[tid];
    __syncthreads();
    int i = blockIdx.x * blockDim.x + tid;
    if (i >= n) return;
    float xv[6];
#pragma unroll
    for (int k = 0; k < 6; k++) xv[k] = x[(size_t)i * 6 + k];
    float dv = g_dinv[i];
    size_t base = (size_t)i * 32;
#pragma unroll
    for (int c = 0; c < 32; c++) {
        float acc = 0.f;
#pragma unroll
        for (int k = 0; k < 6; k++) acc = fmaf(xv[k], Ws[k * 32 + c], acc);
        g_A[base + c] = dv * acc;
    }
}

// agg32: o1 = dinv_d * sum hs + b1 ; stats1 ; write w1 = o1 * dinv_d -> g_B [N,32]
// edge loop unrolled x4 for MLP
__global__ void agg32_kernel(const float* __restrict__ bias, int n) {
    __shared__ float sred[64];
    int tid = threadIdx.x;
    if (tid < 64) sred[tid] = 0.f;
    __syncthreads();
    int lane = tid & 31;
    int nw = (gridDim.x * blockDim.x) >> 5;
    int gw = (blockIdx.x * blockDim.x + tid) >> 5;
    float b = bias[lane];
    float ps = 0.f, pq = 0.f;
    for (int d = gw; d < n; d += nw) {
        float acc = g_A[(size_t)d * 32 + lane];
        int beg = g_rowptr[d], end = g_rowptr[d + 1];
        int j = beg;
        float acc2 = 0.f, acc3 = 0.f, acc4 = 0.f;
        for (; j + 3 < end; j += 4) {
            int s0 = g_col[j], s1 = g_col[j + 1], s2 = g_col[j + 2], s3 = g_col[j + 3];
            float v0 = g_A[(size_t)s0 * 32 + lane];
            float v1 = g_A[(size_t)s1 * 32 + lane];
            float v2 = g_A[(size_t)s2 * 32 + lane];
            float v3 = g_A[(size_t)s3 * 32 + lane];
            acc += v0; acc2 += v1; acc3 += v2; acc4 += v3;
        }
        for (; j < end; j++) acc += g_A[(size_t)g_col[j] * 32 + lane];
        acc += (acc2 + acc3) + acc4;
        float dv = g_dinv[d];
        float o = fmaf(dv, acc, b);
        g_B[(size_t)d * 32 + lane] = o * dv;   // w1
        ps += o; pq += o * o;
    }
    atomicAdd(&sred[lane], ps);
    atomicAdd(&sred[32 + lane], pq);
    __syncthreads();
    if (tid < 64) atomicAdd(&g_stats[tid], sred[tid]);
}

// ------------------------------- layer 2 (fused gather+gemm) -----------------
__global__ void layer2_kernel(const float* __restrict__ W, const float* __restrict__ bias,
                              const float* __restrict__ gamma, const float* __restrict__ beta,
                              float invn, int n) {
    __shared__ float Ws[32 * 64];
    __shared__ float ssc[32], ssh[32];
    __shared__ float sred[128];
    int tid = threadIdx.x;
    for (int i = tid; i < 32 * 64; i += blockDim.x) Ws[i] = W[i];
    if (tid < 32) {
        float m = g_stats[tid] * invn;
        float var = g_stats[32 + tid] * invn - m * m;
        float s = gamma[tid] * rsqrtf(var + 1e-5f);
        ssc[tid] = s;
        ssh[tid] = fmaf(-m, s, beta[tid]);
    }
    if (tid < 128) sred[tid] = 0.f;
    __syncthreads();
    int lane = tid & 31;
    int nw = (gridDim.x * blockDim.x) >> 5;
    int gw = (blockIdx.x * blockDim.x + tid) >> 5;
    float sc = ssc[lane], sh = ssh[lane];
    float b0 = bias[lane], b1 = bias[32 + lane];
    float ps0 = 0.f, ps1 = 0.f, pq0 = 0.f, pq1 = 0.f;
    for (int d = gw; d < n; d += nw) {
        float dvd = g_dinv[d];
        float w = g_B[(size_t)d * 32 + lane];
        float u = fmaxf(fmaf(sc, w, sh * dvd), 0.f);       // self term
        int beg = g_rowptr[d], end = g_rowptr[d + 1];
        int j = beg;
        float u2 = 0.f, u3 = 0.f, u4 = 0.f;
        for (; j + 3 < end; j += 4) {
            int s0 = g_col[j], s1 = g_col[j + 1], s2 = g_col[j + 2], s3 = g_col[j + 3];
            float e0 = g_edinv[j],     e1 = g_edinv[j + 1];
            float e2 = g_edinv[j + 2], e3 = g_edinv[j + 3];
            float v0 = g_B[(size_t)s0 * 32 + lane];
            float v1 = g_B[(size_t)s1 * 32 + lane];
            float v2 = g_B[(size_t)s2 * 32 + lane];
            float v3 = g_B[(size_t)s3 * 32 + lane];
            u  += fmaxf(fmaf(sc, v0, sh * e0), 0.f);
            u2 += fmaxf(fmaf(sc, v1, sh * e1), 0.f);
            u3 += fmaxf(fmaf(sc, v2, sh * e2), 0.f);
            u4 += fmaxf(fmaf(sc, v3, sh * e3), 0.f);
        }
        for (; j < end; j++) {
            float v = g_B[(size_t)g_col[j] * 32 + lane];
            u += fmaxf(fmaf(sc, v, sh * g_edinv[j]), 0.f);
        }
        u += (u2 + u3) + u4;
        float a0 = 0.f, a1 = 0.f;
#pragma unroll
        for (int k = 0; k < 32; k++) {
            float v = __shfl_sync(0xffffffffu, u, k);
            a0 = fmaf(v, Ws[k * 64 + lane], a0);
            a1 = fmaf(v, Ws[k * 64 + 32 + lane], a1);
        }
        float o0 = fmaf(a0, dvd, b0);
        float o1 = fmaf(a1, dvd, b1);
        size_t ob = (size_t)d * 64;
        g_A[ob + lane] = o0 * dvd;       // w2
        g_A[ob + 32 + lane] = o1 * dvd;
        ps0 += o0; ps1 += o1; pq0 += o0 * o0; pq1 += o1 * o1;
    }
    atomicAdd(&sred[lane], ps0);
    atomicAdd(&sred[32 + lane], ps1);
    atomicAdd(&sred[64 + lane], pq0);
    atomicAdd(&sred[96 + lane], pq1);
    __syncthreads();
    if (tid < 128) atomicAdd(&g_stats[64 + tid], sred[tid]);
}

// ------------------------------- layer 3 (fused gather+gemm+pool) ------------
__global__ void layer3_kernel(const float* __restrict__ W, const float* __restrict__ bias,
                              const float* __restrict__ gamma, const float* __restrict__ beta,
                              const int* __restrict__ batch, float invn, int n) {
    __shared__ float Ws[64 * 128];   // 32 KB
    __shared__ float ssc[64], ssh[64];
    __shared__ float sred[256];
    int tid = threadIdx.x;
    for (int i = tid; i < 64 * 128; i += blockDim.x) Ws[i] = W[i];
    if (tid < 64) {
        float m = g_stats[64 + tid] * invn;
        float var = g_stats[128 + tid] * invn - m * m;
        float s = gamma[tid] * rsqrtf(var + 1e-5f);
        ssc[tid] = s;
        ssh[tid] = fmaf(-m, s, beta[tid]);
    }
    if (tid < 256) sred[tid] = 0.f;
    __syncthreads();
    int lane = tid & 31;
    int nwarp = (gridDim.x * blockDim.x) >> 5;
    int w = (blockIdx.x * blockDim.x + tid) >> 5;
    int chunk = (n + nwarp - 1) / nwarp;
    int beg_d = w * chunk;
    int end_d = min(beg_d + chunk, n);
    int c0 = lane * 2;
    float sc0 = ssc[c0], sc1 = ssc[c0 + 1];
    float sh0 = ssh[c0], sh1 = ssh[c0 + 1];
    float bb0 = bias[lane], bb1 = bias[32 + lane];
    float bb2 = bias[64 + lane], bb3 = bias[96 + lane];
    float ps[4] = {0.f, 0.f, 0.f, 0.f};
    float pq[4] = {0.f, 0.f, 0.f, 0.f};
    float m0 = -INFINITY, m1 = -INFINITY, m2 = -INFINITY, m3 = -INFINITY;
    int cur = -1;
    for (int d = beg_d; d < end_d; d++) {
        int bg = batch[d];
        if (bg != cur) {
            if (cur >= 0) {
                atomicMax(&g_poolu[cur * 128 + lane],      enc_f(m0));
                atomicMax(&g_poolu[cur * 128 + 32 + lane], enc_f(m1));
                atomicMax(&g_poolu[cur * 128 + 64 + lane], enc_f(m2));
                atomicMax(&g_poolu[cur * 128 + 96 + lane], enc_f(m3));
            }
            cur = bg;
            m0 = m1 = m2 = m3 = -INFINITY;
        }
        float dvd = g_dinv[d];
        float2 ww = *(const float2*)&g_A[(size_t)d * 64 + c0];
        float ax = fmaxf(fmaf(sc0, ww.x, sh0 * dvd), 0.f);
        float ay = fmaxf(fmaf(sc1, ww.y, sh1 * dvd), 0.f);
        int jb = g_rowptr[d], je = g_rowptr[d + 1];
        int j = jb;
        float ax2 = 0.f, ay2 = 0.f;
        for (; j + 1 < je; j += 2) {
            int s0 = g_col[j], s1 = g_col[j + 1];
            float e0 = g_edinv[j], e1 = g_edinv[j + 1];
            float2 v0 = *(const float2*)&g_A[(size_t)s0 * 64 + c0];
            float2 v1 = *(const float2*)&g_A[(size_t)s1 * 64 + c0];
            ax  += fmaxf(fmaf(sc0, v0.x, sh0 * e0), 0.f);
            ay  += fmaxf(fmaf(sc1, v0.y, sh1 * e0), 0.f);
            ax2 += fmaxf(fmaf(sc0, v1.x, sh0 * e1), 0.f);
            ay2 += fmaxf(fmaf(sc1, v1.y, sh1 * e1), 0.f);
        }
        for (; j < je; j++) {
            int s = g_col[j];
            float ed = g_edinv[j];
            float2 v = *(const float2*)&g_A[(size_t)s * 64 + c0];
            ax += fmaxf(fmaf(sc0, v.x, sh0 * ed), 0.f);
            ay += fmaxf(fmaf(sc1, v.y, sh1 * ed), 0.f);
        }
        ax += ax2; ay += ay2;
        // GEMM: channel 2k held by lane k (.x), channel 2k+1 by lane k (.y)
        float a0 = 0.f, a1 = 0.f, a2 = 0.f, a3 = 0.f;
#pragma unroll
        for (int kk = 0; kk < 32; kk++) {
            float vx = __shfl_sync(0xffffffffu, ax, kk);
            float vy = __shfl_sync(0xffffffffu, ay, kk);
            const float* w0 = &Ws[(2 * kk) * 128];
            const float* w1 = &Ws[(2 * kk + 1) * 128];
            a0 = fmaf(vx, w0[lane], a0);       a0 = fmaf(vy, w1[lane], a0);
            a1 = fmaf(vx, w0[32 + lane], a1);  a1 = fmaf(vy, w1[32 + lane], a1);
            a2 = fmaf(vx, w0[64 + lane], a2);  a2 = fmaf(vy, w1[64 + lane], a2);
            a3 = fmaf(vx, w0[96 + lane], a3);  a3 = fmaf(vy, w1[96 + lane], a3);
        }
        float o0 = fmaf(a0, dvd, bb0);
        float o1 = fmaf(a1, dvd, bb1);
        float o2 = fmaf(a2, dvd, bb2);
        float o3 = fmaf(a3, dvd, bb3);
        ps[0] += o0; ps[1] += o1; ps[2] += o2; ps[3] += o3;
        pq[0] += o0 * o0; pq[1] += o1 * o1; pq[2] += o2 * o2; pq[3] += o3 * o3;
        m0 = fmaxf(m0, o0); m1 = fmaxf(m1, o1);
        m2 = fmaxf(m2, o2); m3 = fmaxf(m3, o3);
    }
    if (cur >= 0) {
        atomicMax(&g_poolu[cur * 128 + lane],      enc_f(m0));
        atomicMax(&g_poolu[cur * 128 + 32 + lane], enc_f(m1));
        atomicMax(&g_poolu[cur * 128 + 64 + lane], enc_f(m2));
        atomicMax(&g_poolu[cur * 128 + 96 + lane], enc_f(m3));
    }
    atomicAdd(&sred[lane], ps[0]);
    atomicAdd(&sred[32 + lane], ps[1]);
    atomicAdd(&sred[64 + lane], ps[2]);
    atomicAdd(&sred[96 + lane], ps[3]);
    atomicAdd(&sred[128 + lane], pq[0]);
    atomicAdd(&sred[160 + lane], pq[1]);
    atomicAdd(&sred[192 + lane], pq[2]);
    atomicAdd(&sred[224 + lane], pq[3]);
    __syncthreads();
    if (tid < 256) atomicAdd(&g_stats[192 + tid], sred[tid]);
}

// --------------------------------- final MLP ----------------------------------
__global__ void fc1_kernel(const float* __restrict__ Wf1, const float* __restrict__ bf1,
                           const float* __restrict__ g3, const float* __restrict__ be3,
                           float invn) {
    __shared__ float pr[128];
    int g = blockIdx.x, t = threadIdx.x;
    {
        float mm = g_stats[192 + t] * invn;
        float var = g_stats[320 + t] * invn - mm * mm;
        float s = g3[t] * rsqrtf(var + 1e-5f);
        float sh = fmaf(-mm, s, be3[t]);
        float raw = dec_f(g_poolu[g * 128 + t]);
        pr[t] = fmaxf(fmaf(s, raw, sh), 0.f);
    }
    __syncthreads();
    float acc = bf1[t];
#pragma unroll 8
    for (int k = 0; k < 128; k++) acc = fmaf(pr[k], Wf1[k * 128 + t], acc);
    g_q[g * 128 + t] = acc;
    atomicAdd(&g_stats[448 + t], acc);
    atomicAdd(&g_stats[576 + t], acc * acc);
}

__global__ void fc2_kernel(const float* __restrict__ Wf2, const float* __restrict__ bf2,
                           const float* __restrict__ g4, const float* __restrict__ be4,
                           float* __restrict__ out) {
    __shared__ float r[128];
    __shared__ float red[64];
    int g = blockIdx.x, t = threadIdx.x;  // 64 threads
    const float invg = 1.0f / (float)NGRAPH;
#pragma unroll
    for (int h = 0; h < 2; h++) {
        int c = t + 64 * h;
        float mm = g_stats[448 + c] * invg;
        float var = g_stats[576 + c] * invg - mm * mm;
        float s = g4[c] * rsqrtf(var + 1e-5f);
        float sh = fmaf(-mm, s, be4[c]);
        r[c] = fmaxf(fmaf(s, g_q[g * 128 + c], sh), 0.f);
    }
    __syncthreads();
    float acc = bf2[t];
#pragma unroll 8
    for (int k = 0; k < 128; k++) acc = fmaf(r[k], Wf2[k * 64 + t], acc);
    red[t] = acc * acc;
    for (int off = 32; off > 0; off >>= 1) {
        __syncthreads();
        if (t < off) red[t] += red[t + off];
    }
    __syncthreads();
    float denom = fmaxf(sqrtf(red[0]), 1e-12f);
    out[g * 64 + t] = acc / denom;
}

// --------------------------------- launcher -----------------------------------
extern "C" void kernel_launch(void* const* d_in, const int* in_sizes, int n_in,
                              void* d_out, int out_size) {
    const float* x    = (const float*)d_in[0];
    const int* src    = (const int*)d_in[1];
    const int* dst    = (const int*)d_in[2];
    const int* batch  = (const int*)d_in[3];
    const float* W1  = (const float*)d_in[4];
    const float* b1  = (const float*)d_in[5];
    const float* G1  = (const float*)d_in[6];
    const float* be1 = (const float*)d_in[7];
    const float* W2  = (const float*)d_in[8];
    const float* b2  = (const float*)d_in[9];
    const float* G2  = (const float*)d_in[10];
    const float* be2 = (const float*)d_in[11];
    const float* W3  = (const float*)d_in[12];
    const float* b3  = (const float*)d_in[13];
    const float* G3  = (const float*)d_in[14];
    const float* be3 = (const float*)d_in[15];
    const float* Wf1 = (const float*)d_in[16];
    const float* bf1 = (const float*)d_in[17];
    const float* G4  = (const float*)d_in[18];
    const float* be4 = (const float*)d_in[19];
    const float* Wf2 = (const float*)d_in[20];
    const float* bf2 = (const float*)d_in[21];

    int n = in_sizes[0] / 6;
    int e = in_sizes[1];
    int nb = (n + 1023) / 1024;
    float invn = 1.0f / (float)n;

    int zmax = n > NGRAPH * 128 ? n : NGRAPH * 128;
    zero_kernel<<<(zmax + 255) / 256, 256>>>(n);
    deg_kernel<<<(e + 255) / 256, 256>>>(dst, e);
    scan_block_kernel<<<nb, 1024>>>(n);
    scan_fin2_kernel<<<nb, 1024>>>(n, nb);
    fill_kernel<<<(e + 255) / 256, 256>>>(src, dst, e);

    // Layer 1
    gemm1_kernel<<<(n + 255) / 256, 256>>>(x, W1, n);
    agg32_kernel<<<2048, 256>>>(b1, n);
    // Layer 2 fused (gather 32-wide + GEMM 32x64)
    layer2_kernel<<<2048, 256>>>(W2, b2, G1, be1, invn, n);
    // Layer 3 fused (gather 64-wide + GEMM 64x128 + stats + pool)
    layer3_kernel<<<2048, 256>>>(W3, b3, G2, be2, batch, invn, n);
    // MLP head
    fc1_kernel<<<NGRAPH, 128>>>(Wf1, bf1, G3, be3, invn);
    fc2_kernel<<<NGRAPH, 64>>>(Wf2, bf2, G4, be4, (float*)d_out);
}